// round 6
// baseline (speedup 1.0000x reference)
#include <cuda_runtime.h>
#include <cuda_fp16.h>
#include <mma.h>
#include <cstdint>

using namespace nvcuda;

#define NN 100000
#define NE_CAP 1600000
#define NF 128
#define FO3 40
#define FO3P 48  // padded layer-3 width for wmma tiles

typedef unsigned long long u64;

// ---------------- device scratch ----------------
__device__ float  g_deg[NN];
__device__ __half g_hh[(size_t)NN * NF];    // fp16 h (layers 1,2)
__device__ float  g_h32[(size_t)NN * NF];   // fp32 h layer 3 (padded width 48)
__device__ __half g_yh[(size_t)NN * NF];    // fp16 y (agg outputs, layers 1,2)
__device__ __half g_w2h[NF * NF];           // fp16 W2
__device__ __half g_w3h[NF * FO3P];         // fp16 W3 padded
__device__ int2   g_sd[NE_CAP];
__device__ int2   g_epack[NE_CAP];
__device__ int    g_rowptr[NN + 1];
__device__ int    g_cur[NN];
__device__ int    g_cnt[NN];
__device__ int    g_bsum[128];
__device__ int    g_is32;

// ---------------- f32x2 helpers (layer-1 FFMA2 GEMM) ----------------
__device__ __forceinline__ void ffma2(u64& d, u64 a, u64 b) {
    asm("fma.rn.f32x2 %0, %1, %2, %0;" : "+l"(d) : "l"(a), "l"(b));
}
__device__ __forceinline__ u64 dup2(float x) {
    u64 r; asm("mov.b64 %0, {%1, %1};" : "=l"(r) : "f"(x)); return r;
}
__device__ __forceinline__ float2 upk2(u64 v) {
    float2 r; asm("mov.b64 {%0, %1}, %2;" : "=f"(r.x), "=f"(r.y) : "l"(v)); return r;
}

// ---------------- setup kernels ----------------
__global__ void k_detect(const long long* __restrict__ raw, int nE) {
    int i = blockIdx.x * blockDim.x + threadIdx.x;
    int lim = nE < 4096 ? nE : 4096;
    if (i < lim) {
        long long v = raw[i];
        if (v < 0 || v >= (1LL << 30)) atomicOr(&g_is32, 1);
    }
}

__global__ void k_cvtW2(const float* __restrict__ W, __half* __restrict__ Wh) {
    int i = blockIdx.x * blockDim.x + threadIdx.x;
    if (i < NF * NF) Wh[i] = __float2half(W[i]);
}

__global__ void k_cvtW3(const float* __restrict__ W, __half* __restrict__ Wh) {
    int i = blockIdx.x * blockDim.x + threadIdx.x;
    if (i < NF * FO3P) {
        int r = i / FO3P, c = i - r * FO3P;
        Wh[i] = (c < FO3) ? __float2half(W[r * FO3 + c]) : __half(0);
    }
}

__global__ void k_prep(const void* __restrict__ raw, const float* __restrict__ ew,
                       float* deg, int* cnt, int nE) {
    int e = blockIdx.x * blockDim.x + threadIdx.x;
    if (e >= nE) return;
    int s, d;
    if (g_is32) {
        const int* p = (const int*)raw;
        s = p[e]; d = p[(size_t)nE + e];
    } else {
        const long long* p = (const long long*)raw;
        s = (int)p[e]; d = (int)p[(size_t)nE + e];
    }
    g_sd[e] = make_int2(s, d);
    atomicAdd(&deg[d], ew[e]);
    atomicAdd(&cnt[d], 1);
}

__global__ void k_dinv(float* deg, int n) {
    int i = blockIdx.x * blockDim.x + threadIdx.x;
    if (i < n) deg[i] = rsqrtf(deg[i] + 1.0f);
}

__global__ void k_scanA(const int* __restrict__ cnt, int* rowptr, int* bsum, int n) {
    __shared__ int s[1024];
    int t = threadIdx.x, i = blockIdx.x * 1024 + t;
    int v = (i < n) ? cnt[i] : 0;
    s[t] = v;
    __syncthreads();
#pragma unroll
    for (int off = 1; off < 1024; off <<= 1) {
        int x = (t >= off) ? s[t - off] : 0;
        __syncthreads();
        s[t] += x;
        __syncthreads();
    }
    if (i < n) rowptr[i] = s[t] - v;
    if (t == 1023) bsum[blockIdx.x] = s[1023];
}

__global__ void k_scanB(int* bsum, int nb) {
    __shared__ int s[128];
    int t = threadIdx.x;
    int v = (t < nb) ? bsum[t] : 0;
    s[t] = v;
    __syncthreads();
#pragma unroll
    for (int off = 1; off < 128; off <<= 1) {
        int x = (t >= off) ? s[t - off] : 0;
        __syncthreads();
        s[t] += x;
        __syncthreads();
    }
    if (t < nb) bsum[t] = s[t] - v;
}

__global__ void k_scanC(int* rowptr, const int* __restrict__ bsum, int* cur,
                        int n, int nE) {
    int i = blockIdx.x * blockDim.x + threadIdx.x;
    if (i < n) {
        int v = rowptr[i] + bsum[i >> 10];
        rowptr[i] = v;
        cur[i] = v;
    }
    if (i == 0) rowptr[n] = nE;
}

__global__ void k_place(const float* __restrict__ ew, const float* __restrict__ dinv,
                        int nE) {
    int e = blockIdx.x * blockDim.x + threadIdx.x;
    if (e >= nE) return;
    int2 sd = g_sd[e];
    int p = atomicAdd(&g_cur[sd.y], 1);
    float norm = ew[e] * dinv[sd.x] * dinv[sd.y];
    g_epack[p] = make_int2(sd.x, __float_as_int(norm));
}

// ---------------- layer-1 GEMM (fp32 in, FFMA2) -> fp16 h ----------------
__global__ void __launch_bounds__(256, 2)
k_gemm128_f32(const float* __restrict__ X, const float* __restrict__ W,
              __half* __restrict__ Hh, int n) {
    extern __shared__ float sm[];
    float* Ws = sm;
    float* Xs = sm + NF * NF;
    int tid = threadIdx.x, warp = tid >> 5, lane = tid & 31;

    for (int i = tid; i < NF * NF / 4; i += 256)
        ((float4*)Ws)[i] = ((const float4*)W)[i];

    int row0 = blockIdx.x * 64 + warp * 8;
    float* xs = Xs + warp * (8 * NF);
#pragma unroll
    for (int r = 0; r < 8; r++) {
        int row = row0 + r;
        float4 v = make_float4(0.f, 0.f, 0.f, 0.f);
        if (row < n) v = ((const float4*)(X + (size_t)row * NF))[lane];
        ((float4*)(xs + r * NF))[lane] = v;
    }
    __syncthreads();

    u64 acc[8][2];
#pragma unroll
    for (int r = 0; r < 8; r++) { acc[r][0] = 0ull; acc[r][1] = 0ull; }

    const float* wl = Ws + 4 * lane;
    for (int k4 = 0; k4 < NF; k4 += 4) {
        float4 xv[8];
#pragma unroll
        for (int r = 0; r < 8; r++)
            xv[r] = *(const float4*)(xs + r * NF + k4);
#pragma unroll
        for (int kk = 0; kk < 4; kk++) {
            const float* wp = wl + (k4 + kk) * NF;
            u64 w01 = *(const u64*)(wp);
            u64 w23 = *(const u64*)(wp + 2);
#pragma unroll
            for (int r = 0; r < 8; r++) {
                float xk = kk == 0 ? xv[r].x : kk == 1 ? xv[r].y
                         : kk == 2 ? xv[r].z : xv[r].w;
                u64 xk2 = dup2(xk);
                ffma2(acc[r][0], xk2, w01);
                ffma2(acc[r][1], xk2, w23);
            }
        }
    }
#pragma unroll
    for (int r = 0; r < 8; r++) {
        int row = row0 + r;
        if (row < n) {
            float2 a = upk2(acc[r][0]), b = upk2(acc[r][1]);
            __half2 h01 = __floats2half2_rn(a.x, a.y);
            __half2 h23 = __floats2half2_rn(b.x, b.y);
            ((uint2*)(Hh + (size_t)row * NF))[lane] =
                make_uint2(*(unsigned*)&h01, *(unsigned*)&h23);
        }
    }
}

// ---------------- tensor-core GEMM fout=128 (fp16 in/out, fp32 acc) ----------------
// 64 rows/block, 8 warps in 4x2: warp_m rows 16, warp_n 64 cols (4 wmma tiles).
__global__ void __launch_bounds__(256, 2)
k_gemm128_tc(const __half* __restrict__ X, const __half* __restrict__ W,
             __half* __restrict__ Hh, int n) {
    extern __shared__ char smc[];
    __half* Ws = (__half*)smc;               // 128x128 fp16 = 32KB
    __half* Xs = (__half*)(smc + 32 * 1024); // 64x128 fp16 = 16KB
    int tid = threadIdx.x, wid = tid >> 5;
    int warp_m = wid >> 1, warp_n = wid & 1;
    int row0 = blockIdx.x * 64;

    // stage W (2048 uint4)
    for (int i = tid; i < 2048; i += 256)
        ((uint4*)Ws)[i] = ((const uint4*)W)[i];
    // stage X with ReLU (64 rows x 16 uint4)
    __half2 z2 = __floats2half2_rn(0.f, 0.f);
    for (int i = tid; i < 1024; i += 256) {
        int row = i >> 4, c = i & 15;
        uint4 v = make_uint4(0, 0, 0, 0);
        if (row0 + row < n) {
            v = ((const uint4*)(X + (size_t)(row0 + row) * NF))[c];
            __half2* hv = (__half2*)&v;
            hv[0] = __hmax2(hv[0], z2); hv[1] = __hmax2(hv[1], z2);
            hv[2] = __hmax2(hv[2], z2); hv[3] = __hmax2(hv[3], z2);
        }
        ((uint4*)Xs)[i] = v;
    }
    __syncthreads();

    wmma::fragment<wmma::accumulator, 16, 16, 16, float> c[4];
#pragma unroll
    for (int j = 0; j < 4; j++) wmma::fill_fragment(c[j], 0.f);

#pragma unroll
    for (int k0 = 0; k0 < NF; k0 += 16) {
        wmma::fragment<wmma::matrix_a, 16, 16, 16, __half, wmma::row_major> a;
        wmma::load_matrix_sync(a, Xs + warp_m * 16 * NF + k0, NF);
#pragma unroll
        for (int j = 0; j < 4; j++) {
            wmma::fragment<wmma::matrix_b, 16, 16, 16, __half, wmma::row_major> b;
            wmma::load_matrix_sync(b, Ws + k0 * NF + warp_n * 64 + j * 16, NF);
            wmma::mma_sync(c[j], a, b, c[j]);
        }
    }
    __syncthreads();
    float* Cs = (float*)smc;  // 64x128 fp32 = 32KB (overwrites Ws)
#pragma unroll
    for (int j = 0; j < 4; j++)
        wmma::store_matrix_sync(Cs + warp_m * 16 * NF + warp_n * 64 + j * 16,
                                c[j], NF, wmma::mem_row_major);
    __syncthreads();

    for (int i = tid; i < 64 * 32; i += 256) {
        int row = i >> 5, g = i & 31;
        if (row0 + row < n) {
            float4 v = ((const float4*)Cs)[i];
            __half2 h01 = __floats2half2_rn(v.x, v.y);
            __half2 h23 = __floats2half2_rn(v.z, v.w);
            ((uint2*)(Hh + (size_t)(row0 + row) * NF))[g] =
                make_uint2(*(unsigned*)&h01, *(unsigned*)&h23);
        }
    }
}

// ---------------- tensor-core GEMM fout=48(pad of 40), fp32 out ----------------
// 128 rows/block, 8 warps: warp wid rows 16, all 48 cols (3 tiles).
__global__ void __launch_bounds__(256, 2)
k_gemm40_tc(const __half* __restrict__ X, const __half* __restrict__ W,
            float* __restrict__ H, int n) {
    extern __shared__ char smc[];
    __half* Ws = (__half*)smc;               // 128x48 fp16 = 12KB
    __half* Xs = (__half*)(smc + 12 * 1024); // 128x128 fp16 = 32KB
    int tid = threadIdx.x, wid = tid >> 5;
    int row0 = blockIdx.x * 128;

    for (int i = tid; i < NF * FO3P / 8; i += 256)
        ((uint4*)Ws)[i] = ((const uint4*)W)[i];
    __half2 z2 = __floats2half2_rn(0.f, 0.f);
    for (int i = tid; i < 2048; i += 256) {
        int row = i >> 4, c = i & 15;
        uint4 v = make_uint4(0, 0, 0, 0);
        if (row0 + row < n) {
            v = ((const uint4*)(X + (size_t)(row0 + row) * NF))[c];
            __half2* hv = (__half2*)&v;
            hv[0] = __hmax2(hv[0], z2); hv[1] = __hmax2(hv[1], z2);
            hv[2] = __hmax2(hv[2], z2); hv[3] = __hmax2(hv[3], z2);
        }
        ((uint4*)Xs)[i] = v;
    }
    __syncthreads();

    wmma::fragment<wmma::accumulator, 16, 16, 16, float> c[3];
#pragma unroll
    for (int j = 0; j < 3; j++) wmma::fill_fragment(c[j], 0.f);

#pragma unroll
    for (int k0 = 0; k0 < NF; k0 += 16) {
        wmma::fragment<wmma::matrix_a, 16, 16, 16, __half, wmma::row_major> a;
        wmma::load_matrix_sync(a, Xs + wid * 16 * NF + k0, NF);
#pragma unroll
        for (int j = 0; j < 3; j++) {
            wmma::fragment<wmma::matrix_b, 16, 16, 16, __half, wmma::row_major> b;
            wmma::load_matrix_sync(b, Ws + k0 * FO3P + j * 16, FO3P);
            wmma::mma_sync(c[j], a, b, c[j]);
        }
    }
    __syncthreads();
    float* Cs = (float*)smc;  // 128x48 fp32 = 24KB
#pragma unroll
    for (int j = 0; j < 3; j++)
        wmma::store_matrix_sync(Cs + wid * 16 * FO3P + j * 16, c[j], FO3P,
                                wmma::mem_row_major);
    __syncthreads();

    // write padded h32 (stride 48), float2 granularity: 128*24 groups
    for (int i = tid; i < 128 * 24; i += 256) {
        int row = i / 24, g = i - row * 24;
        if (row0 + row < n)
            ((float2*)(H + (size_t)(row0 + row) * FO3P))[g] = ((const float2*)Cs)[i];
    }
}

// ---------------- aggregation fp16, 2 warps/node (layers 1,2) ----------------
__global__ void k_agg128h(const __half* __restrict__ h, const float* __restrict__ bias,
                          const float* __restrict__ dinv, __half* __restrict__ outh,
                          int n) {
    int gw = (blockIdx.x * blockDim.x + threadIdx.x) >> 5;
    int node = gw >> 1, half = gw & 1;
    int lane = threadIdx.x & 31;
    if (node >= n) return;
    const unsigned* h1 = (const unsigned*)h;  // 64 uints (=128 halves) per row
    int coff = half * 32 + lane;              // uint column
    float dv = dinv[node];
    float selfn = dv * dv;

    unsigned sp = __ldg(&h1[(size_t)node * 64 + coff]);
    float2 s01 = __half22float2(*(const __half2*)&sp);
    float2 acc0 = make_float2(s01.x * selfn, s01.y * selfn);
    float2 acc1 = make_float2(0.f, 0.f);

    int p = g_rowptr[node], p1 = g_rowptr[node + 1];
    for (; p + 4 <= p1; p += 4) {
        int2 e0 = g_epack[p],     e1 = g_epack[p + 1];
        int2 e2 = g_epack[p + 2], e3 = g_epack[p + 3];
        unsigned a = __ldg(&h1[(size_t)e0.x * 64 + coff]);
        unsigned b = __ldg(&h1[(size_t)e1.x * 64 + coff]);
        unsigned c = __ldg(&h1[(size_t)e2.x * 64 + coff]);
        unsigned d = __ldg(&h1[(size_t)e3.x * 64 + coff]);
        float n0 = __int_as_float(e0.y), n1 = __int_as_float(e1.y);
        float n2 = __int_as_float(e2.y), n3 = __int_as_float(e3.y);
        float2 av = __half22float2(*(const __half2*)&a);
        float2 bv2 = __half22float2(*(const __half2*)&b);
        float2 cv = __half22float2(*(const __half2*)&c);
        float2 dvv = __half22float2(*(const __half2*)&d);
        acc0.x = fmaf(av.x, n0, acc0.x);  acc0.y = fmaf(av.y, n0, acc0.y);
        acc1.x = fmaf(bv2.x, n1, acc1.x); acc1.y = fmaf(bv2.y, n1, acc1.y);
        acc0.x = fmaf(cv.x, n2, acc0.x);  acc0.y = fmaf(cv.y, n2, acc0.y);
        acc1.x = fmaf(dvv.x, n3, acc1.x); acc1.y = fmaf(dvv.y, n3, acc1.y);
    }
    for (; p < p1; p++) {
        int2 e0 = g_epack[p];
        unsigned a = __ldg(&h1[(size_t)e0.x * 64 + coff]);
        float n0 = __int_as_float(e0.y);
        float2 av = __half22float2(*(const __half2*)&a);
        acc0.x = fmaf(av.x, n0, acc0.x); acc0.y = fmaf(av.y, n0, acc0.y);
    }
    float2 bv = ((const float2*)bias)[coff];
    acc0.x += acc1.x + bv.x; acc0.y += acc1.y + bv.y;
    __half2 o = __floats2half2_rn(acc0.x, acc0.y);
    ((unsigned*)outh)[(size_t)node * 64 + coff] = *(unsigned*)&o;
}

// ---------------- aggregation fp32, fout=40 (reads padded stride 48) ----------------
__global__ void k_agg40(const float* __restrict__ h, const float* __restrict__ bias,
                        const float* __restrict__ dinv, float* __restrict__ out,
                        int n) {
    int node = (blockIdx.x * blockDim.x + threadIdx.x) >> 5;
    int lane = threadIdx.x & 31;
    if (node >= n || lane >= 20) return;
    float dv = dinv[node];
    float selfn = dv * dv;
    float2 sv = __ldg((const float2*)(h + (size_t)node * FO3P) + lane);
    float2 acc0 = make_float2(sv.x * selfn, sv.y * selfn);
    float2 acc1 = make_float2(0.f, 0.f);

    int p = g_rowptr[node], p1 = g_rowptr[node + 1];
    for (; p + 4 <= p1; p += 4) {
        int2 e0 = g_epack[p],     e1 = g_epack[p + 1];
        int2 e2 = g_epack[p + 2], e3 = g_epack[p + 3];
        float2 a = __ldg((const float2*)(h + (size_t)e0.x * FO3P) + lane);
        float2 b = __ldg((const float2*)(h + (size_t)e1.x * FO3P) + lane);
        float2 c = __ldg((const float2*)(h + (size_t)e2.x * FO3P) + lane);
        float2 d = __ldg((const float2*)(h + (size_t)e3.x * FO3P) + lane);
        float n0 = __int_as_float(e0.y), n1 = __int_as_float(e1.y);
        float n2 = __int_as_float(e2.y), n3 = __int_as_float(e3.y);
        acc0.x = fmaf(a.x, n0, acc0.x); acc0.y = fmaf(a.y, n0, acc0.y);
        acc1.x = fmaf(b.x, n1, acc1.x); acc1.y = fmaf(b.y, n1, acc1.y);
        acc0.x = fmaf(c.x, n2, acc0.x); acc0.y = fmaf(c.y, n2, acc0.y);
        acc1.x = fmaf(d.x, n3, acc1.x); acc1.y = fmaf(d.y, n3, acc1.y);
    }
    for (; p < p1; p++) {
        int2 e0 = g_epack[p];
        float2 a = __ldg((const float2*)(h + (size_t)e0.x * FO3P) + lane);
        float n0 = __int_as_float(e0.y);
        acc0.x = fmaf(a.x, n0, acc0.x); acc0.y = fmaf(a.y, n0, acc0.y);
    }
    float2 bv = ((const float2*)bias)[lane];
    acc0.x += acc1.x + bv.x; acc0.y += acc1.y + bv.y;
    ((float2*)(out + (size_t)node * FO3))[lane] = acc0;  // FO3=40, lane<20 -> exact
}

// ---------------- launch ----------------
extern "C" void kernel_launch(void* const* d_in, const int* in_sizes, int n_in,
                              void* d_out, int out_size) {
    const float* x  = (const float*)d_in[0];
    const void*  ei = d_in[1];
    const float* ew = (const float*)d_in[2];
    const float* W1 = (const float*)d_in[3];
    const float* b1 = (const float*)d_in[4];
    const float* W2 = (const float*)d_in[5];
    const float* b2 = (const float*)d_in[6];
    const float* W3 = (const float*)d_in[7];
    const float* b3 = (const float*)d_in[8];
    int n  = in_sizes[0] / NF;
    int nE = in_sizes[2];
    float* out = (float*)d_out;

    float *dinv, *h32;
    __half *hh, *yh, *w2h, *w3h;
    int *rowptr, *cur, *cnt, *bsum, *is32p;
    cudaGetSymbolAddress((void**)&dinv, g_deg);
    cudaGetSymbolAddress((void**)&hh, g_hh);
    cudaGetSymbolAddress((void**)&h32, g_h32);
    cudaGetSymbolAddress((void**)&yh, g_yh);
    cudaGetSymbolAddress((void**)&w2h, g_w2h);
    cudaGetSymbolAddress((void**)&w3h, g_w3h);
    cudaGetSymbolAddress((void**)&rowptr, g_rowptr);
    cudaGetSymbolAddress((void**)&cur, g_cur);
    cudaGetSymbolAddress((void**)&cnt, g_cnt);
    cudaGetSymbolAddress((void**)&bsum, g_bsum);
    cudaGetSymbolAddress((void**)&is32p, g_is32);

    const int T = 256;
    size_t smemF32 = (size_t)(NF * NF + 8 * 8 * NF) * sizeof(float);  // 96 KB
    size_t smemTC128 = 48 * 1024;
    size_t smemTC40  = 44 * 1024;
    cudaFuncSetAttribute(k_gemm128_f32, cudaFuncAttributeMaxDynamicSharedMemorySize, (int)smemF32);
    cudaFuncSetAttribute(k_gemm128_tc,  cudaFuncAttributeMaxDynamicSharedMemorySize, (int)smemTC128);
    cudaFuncSetAttribute(k_gemm40_tc,   cudaFuncAttributeMaxDynamicSharedMemorySize, (int)smemTC40);

    int gb64  = (n + 63) / 64;
    int gb128 = (n + 127) / 128;
    int ab2 = (n * 2 + 7) / 8;   // agg128h: 2 warps/node, 8 warps/block
    int ab  = (n + 7) / 8;       // agg40
    int nb = (n + 1023) / 1024;

    // Fork: GEMM1 (x@W1, fp32 FFMA2) independent of edge setup
    cudaStream_t s2;
    cudaStreamCreateWithFlags(&s2, cudaStreamNonBlocking);
    cudaEvent_t evF, evJ;
    cudaEventCreateWithFlags(&evF, cudaEventDisableTiming);
    cudaEventCreateWithFlags(&evJ, cudaEventDisableTiming);

    cudaEventRecord(evF, 0);
    cudaStreamWaitEvent(s2, evF, 0);
    k_gemm128_f32<<<gb64, T, smemF32, s2>>>(x, W1, hh, n);
    cudaEventRecord(evJ, s2);

    // Main-stream setup (overlapped with GEMM1)
    cudaMemsetAsync(is32p, 0, sizeof(int), 0);
    cudaMemsetAsync(cnt, 0, (size_t)n * sizeof(int), 0);
    cudaMemsetAsync(dinv, 0, (size_t)n * sizeof(float), 0);
    k_cvtW2<<<(NF * NF + T - 1) / T, T>>>(W2, w2h);
    k_cvtW3<<<(NF * FO3P + T - 1) / T, T>>>(W3, w3h);
    k_detect<<<(4096 + T - 1) / T, T>>>((const long long*)ei, nE);
    k_prep<<<(nE + T - 1) / T, T>>>(ei, ew, dinv, cnt, nE);
    k_dinv<<<(n + T - 1) / T, T>>>(dinv, n);
    k_scanA<<<nb, 1024>>>(cnt, rowptr, bsum, n);
    k_scanB<<<1, 128>>>(bsum, nb);
    k_scanC<<<(n + T - 1) / T, T>>>(rowptr, bsum, cur, n, nE);
    k_place<<<(nE + T - 1) / T, T>>>(ew, dinv, nE);

    cudaStreamWaitEvent(0, evJ, 0);

    // Layer 1 agg
    k_agg128h<<<ab2, T>>>(hh, b1, dinv, yh, n);
    // Layer 2: tensor-core GEMM (ReLU fused) + agg
    k_gemm128_tc<<<gb64, T, smemTC128>>>(yh, w2h, hh, n);
    k_agg128h<<<ab2, T>>>(hh, b2, dinv, yh, n);
    // Layer 3: tensor-core GEMM (padded 48) -> fp32, agg -> d_out
    k_gemm40_tc<<<gb128, T, smemTC40>>>(yh, w3h, h32, n);
    k_agg40<<<ab, T>>>(h32, b3, dinv, out, n);
}

// round 7
// speedup vs baseline: 1.1550x; 1.1550x over previous
#include <cuda_runtime.h>
#include <cuda_fp16.h>
#include <mma.h>
#include <cstdint>

using namespace nvcuda;

#define NN 100000
#define NE_CAP 1600000
#define NF 128
#define FO3 40
#define FO3P 48  // padded layer-3 width for wmma tiles

typedef unsigned long long u64;

// ---------------- device scratch ----------------
__device__ float  g_deg[NN];
__device__ __half g_hh[(size_t)NN * NF];    // fp16 h (layers 1,2)
__device__ float  g_h32[(size_t)NN * NF];   // fp32 h layer 3 (padded width 48)
__device__ __half g_yh[(size_t)NN * NF];    // fp16 y (agg outputs, layers 1,2)
__device__ __half g_w2h[NF * NF];           // fp16 W2
__device__ __half g_w3h[NF * FO3P];         // fp16 W3 padded
__device__ int2   g_sd[NE_CAP];
__device__ int2   g_epack[NE_CAP];
__device__ int    g_rowptr[NN + 1];
__device__ int    g_cur[NN];
__device__ int    g_cnt[NN];
__device__ int    g_bsum[128];
__device__ int    g_is32;

// ---------------- f32x2 helpers (layer-1 FFMA2 GEMM) ----------------
__device__ __forceinline__ void ffma2(u64& d, u64 a, u64 b) {
    asm("fma.rn.f32x2 %0, %1, %2, %0;" : "+l"(d) : "l"(a), "l"(b));
}
__device__ __forceinline__ u64 dup2(float x) {
    u64 r; asm("mov.b64 %0, {%1, %1};" : "=l"(r) : "f"(x)); return r;
}
__device__ __forceinline__ float2 upk2(u64 v) {
    float2 r; asm("mov.b64 {%0, %1}, %2;" : "=f"(r.x), "=f"(r.y) : "l"(v)); return r;
}

// ---------------- setup kernels ----------------
__global__ void k_detect(const long long* __restrict__ raw, int nE) {
    int i = blockIdx.x * blockDim.x + threadIdx.x;
    int lim = nE < 4096 ? nE : 4096;
    if (i < lim) {
        long long v = raw[i];
        if (v < 0 || v >= (1LL << 30)) atomicOr(&g_is32, 1);
    }
}

__global__ void k_cvtW2(const float* __restrict__ W, __half* __restrict__ Wh) {
    int i = blockIdx.x * blockDim.x + threadIdx.x;
    if (i < NF * NF) Wh[i] = __float2half(W[i]);
}

__global__ void k_cvtW3(const float* __restrict__ W, __half* __restrict__ Wh) {
    int i = blockIdx.x * blockDim.x + threadIdx.x;
    if (i < NF * FO3P) {
        int r = i / FO3P, c = i - r * FO3P;
        Wh[i] = (c < FO3) ? __float2half(W[r * FO3 + c]) : __half(0);
    }
}

__global__ void k_prep(const void* __restrict__ raw, const float* __restrict__ ew,
                       float* deg, int* cnt, int nE) {
    int e = blockIdx.x * blockDim.x + threadIdx.x;
    if (e >= nE) return;
    int s, d;
    if (g_is32) {
        const int* p = (const int*)raw;
        s = p[e]; d = p[(size_t)nE + e];
    } else {
        const long long* p = (const long long*)raw;
        s = (int)p[e]; d = (int)p[(size_t)nE + e];
    }
    g_sd[e] = make_int2(s, d);
    atomicAdd(&deg[d], ew[e]);
    atomicAdd(&cnt[d], 1);
}

__global__ void k_dinv(float* deg, int n) {
    int i = blockIdx.x * blockDim.x + threadIdx.x;
    if (i < n) deg[i] = rsqrtf(deg[i] + 1.0f);
}

__global__ void k_scanA(const int* __restrict__ cnt, int* rowptr, int* bsum, int n) {
    __shared__ int s[1024];
    int t = threadIdx.x, i = blockIdx.x * 1024 + t;
    int v = (i < n) ? cnt[i] : 0;
    s[t] = v;
    __syncthreads();
#pragma unroll
    for (int off = 1; off < 1024; off <<= 1) {
        int x = (t >= off) ? s[t - off] : 0;
        __syncthreads();
        s[t] += x;
        __syncthreads();
    }
    if (i < n) rowptr[i] = s[t] - v;
    if (t == 1023) bsum[blockIdx.x] = s[1023];
}

__global__ void k_scanB(int* bsum, int nb) {
    __shared__ int s[128];
    int t = threadIdx.x;
    int v = (t < nb) ? bsum[t] : 0;
    s[t] = v;
    __syncthreads();
#pragma unroll
    for (int off = 1; off < 128; off <<= 1) {
        int x = (t >= off) ? s[t - off] : 0;
        __syncthreads();
        s[t] += x;
        __syncthreads();
    }
    if (t < nb) bsum[t] = s[t] - v;
}

__global__ void k_scanC(int* rowptr, const int* __restrict__ bsum, int* cur,
                        int n, int nE) {
    int i = blockIdx.x * blockDim.x + threadIdx.x;
    if (i < n) {
        int v = rowptr[i] + bsum[i >> 10];
        rowptr[i] = v;
        cur[i] = v;
    }
    if (i == 0) rowptr[n] = nE;
}

__global__ void k_place(const float* __restrict__ ew, const float* __restrict__ dinv,
                        int nE) {
    int e = blockIdx.x * blockDim.x + threadIdx.x;
    if (e >= nE) return;
    int2 sd = g_sd[e];
    int p = atomicAdd(&g_cur[sd.y], 1);
    float norm = ew[e] * dinv[sd.x] * dinv[sd.y];
    g_epack[p] = make_int2(sd.x, __float_as_int(norm));
}

// ---------------- layer-1 GEMM (fp32 in, FFMA2) -> fp16 h ----------------
__global__ void __launch_bounds__(256, 2)
k_gemm128_f32(const float* __restrict__ X, const float* __restrict__ W,
              __half* __restrict__ Hh, int n) {
    extern __shared__ float sm[];
    float* Ws = sm;
    float* Xs = sm + NF * NF;
    int tid = threadIdx.x, warp = tid >> 5, lane = tid & 31;

    for (int i = tid; i < NF * NF / 4; i += 256)
        ((float4*)Ws)[i] = ((const float4*)W)[i];

    int row0 = blockIdx.x * 64 + warp * 8;
    float* xs = Xs + warp * (8 * NF);
#pragma unroll
    for (int r = 0; r < 8; r++) {
        int row = row0 + r;
        float4 v = make_float4(0.f, 0.f, 0.f, 0.f);
        if (row < n) v = ((const float4*)(X + (size_t)row * NF))[lane];
        ((float4*)(xs + r * NF))[lane] = v;
    }
    __syncthreads();

    u64 acc[8][2];
#pragma unroll
    for (int r = 0; r < 8; r++) { acc[r][0] = 0ull; acc[r][1] = 0ull; }

    const float* wl = Ws + 4 * lane;
    for (int k4 = 0; k4 < NF; k4 += 4) {
        float4 xv[8];
#pragma unroll
        for (int r = 0; r < 8; r++)
            xv[r] = *(const float4*)(xs + r * NF + k4);
#pragma unroll
        for (int kk = 0; kk < 4; kk++) {
            const float* wp = wl + (k4 + kk) * NF;
            u64 w01 = *(const u64*)(wp);
            u64 w23 = *(const u64*)(wp + 2);
#pragma unroll
            for (int r = 0; r < 8; r++) {
                float xk = kk == 0 ? xv[r].x : kk == 1 ? xv[r].y
                         : kk == 2 ? xv[r].z : xv[r].w;
                u64 xk2 = dup2(xk);
                ffma2(acc[r][0], xk2, w01);
                ffma2(acc[r][1], xk2, w23);
            }
        }
    }
#pragma unroll
    for (int r = 0; r < 8; r++) {
        int row = row0 + r;
        if (row < n) {
            float2 a = upk2(acc[r][0]), b = upk2(acc[r][1]);
            __half2 h01 = __floats2half2_rn(a.x, a.y);
            __half2 h23 = __floats2half2_rn(b.x, b.y);
            ((uint2*)(Hh + (size_t)row * NF))[lane] =
                make_uint2(*(unsigned*)&h01, *(unsigned*)&h23);
        }
    }
}

// ---------------- tensor-core GEMM fout=128 (fp16 in/out, fp32 acc) ----------------
__global__ void __launch_bounds__(256, 2)
k_gemm128_tc(const __half* __restrict__ X, const __half* __restrict__ W,
             __half* __restrict__ Hh, int n) {
    extern __shared__ char smc[];
    __half* Ws = (__half*)smc;               // 128x128 fp16 = 32KB
    __half* Xs = (__half*)(smc + 32 * 1024); // 64x128 fp16 = 16KB
    int tid = threadIdx.x, wid = tid >> 5;
    int warp_m = wid >> 1, warp_n = wid & 1;
    int row0 = blockIdx.x * 64;

    for (int i = tid; i < 2048; i += 256)
        ((uint4*)Ws)[i] = ((const uint4*)W)[i];
    __half2 z2 = __floats2half2_rn(0.f, 0.f);
    for (int i = tid; i < 1024; i += 256) {
        int row = i >> 4, c = i & 15;
        uint4 v = make_uint4(0, 0, 0, 0);
        if (row0 + row < n) {
            v = ((const uint4*)(X + (size_t)(row0 + row) * NF))[c];
            __half2* hv = (__half2*)&v;
            hv[0] = __hmax2(hv[0], z2); hv[1] = __hmax2(hv[1], z2);
            hv[2] = __hmax2(hv[2], z2); hv[3] = __hmax2(hv[3], z2);
        }
        ((uint4*)Xs)[i] = v;
    }
    __syncthreads();

    wmma::fragment<wmma::accumulator, 16, 16, 16, float> c[4];
#pragma unroll
    for (int j = 0; j < 4; j++) wmma::fill_fragment(c[j], 0.f);

#pragma unroll
    for (int k0 = 0; k0 < NF; k0 += 16) {
        wmma::fragment<wmma::matrix_a, 16, 16, 16, __half, wmma::row_major> a;
        wmma::load_matrix_sync(a, Xs + warp_m * 16 * NF + k0, NF);
#pragma unroll
        for (int j = 0; j < 4; j++) {
            wmma::fragment<wmma::matrix_b, 16, 16, 16, __half, wmma::row_major> b;
            wmma::load_matrix_sync(b, Ws + k0 * NF + warp_n * 64 + j * 16, NF);
            wmma::mma_sync(c[j], a, b, c[j]);
        }
    }
    __syncthreads();
    float* Cs = (float*)smc;  // 64x128 fp32 = 32KB
#pragma unroll
    for (int j = 0; j < 4; j++)
        wmma::store_matrix_sync(Cs + warp_m * 16 * NF + warp_n * 64 + j * 16,
                                c[j], NF, wmma::mem_row_major);
    __syncthreads();

    for (int i = tid; i < 64 * 32; i += 256) {
        int row = i >> 5, g = i & 31;
        if (row0 + row < n) {
            float4 v = ((const float4*)Cs)[i];
            __half2 h01 = __floats2half2_rn(v.x, v.y);
            __half2 h23 = __floats2half2_rn(v.z, v.w);
            ((uint2*)(Hh + (size_t)(row0 + row) * NF))[g] =
                make_uint2(*(unsigned*)&h01, *(unsigned*)&h23);
        }
    }
}

// ---------------- tensor-core GEMM fout=48(pad of 40), fp32 out ----------------
__global__ void __launch_bounds__(256, 2)
k_gemm40_tc(const __half* __restrict__ X, const __half* __restrict__ W,
            float* __restrict__ H, int n) {
    extern __shared__ char smc[];
    __half* Ws = (__half*)smc;               // 128x48 fp16 = 12KB
    __half* Xs = (__half*)(smc + 12 * 1024); // 128x128 fp16 = 32KB
    int tid = threadIdx.x, wid = tid >> 5;
    int row0 = blockIdx.x * 128;

    for (int i = tid; i < NF * FO3P / 8; i += 256)
        ((uint4*)Ws)[i] = ((const uint4*)W)[i];
    __half2 z2 = __floats2half2_rn(0.f, 0.f);
    for (int i = tid; i < 2048; i += 256) {
        int row = i >> 4, c = i & 15;
        uint4 v = make_uint4(0, 0, 0, 0);
        if (row0 + row < n) {
            v = ((const uint4*)(X + (size_t)(row0 + row) * NF))[c];
            __half2* hv = (__half2*)&v;
            hv[0] = __hmax2(hv[0], z2); hv[1] = __hmax2(hv[1], z2);
            hv[2] = __hmax2(hv[2], z2); hv[3] = __hmax2(hv[3], z2);
        }
        ((uint4*)Xs)[i] = v;
    }
    __syncthreads();

    wmma::fragment<wmma::accumulator, 16, 16, 16, float> c[3];
#pragma unroll
    for (int j = 0; j < 3; j++) wmma::fill_fragment(c[j], 0.f);

#pragma unroll
    for (int k0 = 0; k0 < NF; k0 += 16) {
        wmma::fragment<wmma::matrix_a, 16, 16, 16, __half, wmma::row_major> a;
        wmma::load_matrix_sync(a, Xs + wid * 16 * NF + k0, NF);
#pragma unroll
        for (int j = 0; j < 3; j++) {
            wmma::fragment<wmma::matrix_b, 16, 16, 16, __half, wmma::row_major> b;
            wmma::load_matrix_sync(b, Ws + k0 * FO3P + j * 16, FO3P);
            wmma::mma_sync(c[j], a, b, c[j]);
        }
    }
    __syncthreads();
    float* Cs = (float*)smc;  // 128x48 fp32 = 24KB
#pragma unroll
    for (int j = 0; j < 3; j++)
        wmma::store_matrix_sync(Cs + wid * 16 * FO3P + j * 16, c[j], FO3P,
                                wmma::mem_row_major);
    __syncthreads();

    for (int i = tid; i < 128 * 24; i += 256) {
        int row = i / 24, g = i - row * 24;
        if (row0 + row < n)
            ((float2*)(H + (size_t)(row0 + row) * FO3P))[g] = ((const float2*)Cs)[i];
    }
}

// ---------------- aggregation fp16, 1 warp/node (R5 known-good form) ----------------
__global__ void k_agg128h(const __half* __restrict__ h, const float* __restrict__ bias,
                          const float* __restrict__ dinv, __half* __restrict__ outh,
                          int n) {
    int node = (blockIdx.x * blockDim.x + threadIdx.x) >> 5;
    int lane = threadIdx.x & 31;
    if (node >= n) return;
    const uint2* h2 = (const uint2*)h;
    float dv = dinv[node];
    float selfn = dv * dv;

    uint2 sp = __ldg(&h2[(size_t)node * 32 + lane]);
    float2 s01 = __half22float2(*(const __half2*)&sp.x);
    float2 s23 = __half22float2(*(const __half2*)&sp.y);
    float4 acc0 = make_float4(s01.x * selfn, s01.y * selfn,
                              s23.x * selfn, s23.y * selfn);
    float4 acc1 = make_float4(0.f, 0.f, 0.f, 0.f);

    int p = g_rowptr[node], p1 = g_rowptr[node + 1];
    for (; p + 4 <= p1; p += 4) {
        int2 e0 = g_epack[p],     e1 = g_epack[p + 1];
        int2 e2 = g_epack[p + 2], e3 = g_epack[p + 3];
        uint2 a = __ldg(&h2[(size_t)e0.x * 32 + lane]);
        uint2 b = __ldg(&h2[(size_t)e1.x * 32 + lane]);
        uint2 c = __ldg(&h2[(size_t)e2.x * 32 + lane]);
        uint2 d = __ldg(&h2[(size_t)e3.x * 32 + lane]);
        float n0 = __int_as_float(e0.y), n1 = __int_as_float(e1.y);
        float n2 = __int_as_float(e2.y), n3 = __int_as_float(e3.y);
        float2 a01 = __half22float2(*(const __half2*)&a.x);
        float2 a23 = __half22float2(*(const __half2*)&a.y);
        float2 b01 = __half22float2(*(const __half2*)&b.x);
        float2 b23 = __half22float2(*(const __half2*)&b.y);
        float2 c01 = __half22float2(*(const __half2*)&c.x);
        float2 c23 = __half22float2(*(const __half2*)&c.y);
        float2 d01 = __half22float2(*(const __half2*)&d.x);
        float2 d23 = __half22float2(*(const __half2*)&d.y);
        acc0.x = fmaf(a01.x, n0, acc0.x); acc0.y = fmaf(a01.y, n0, acc0.y);
        acc0.z = fmaf(a23.x, n0, acc0.z); acc0.w = fmaf(a23.y, n0, acc0.w);
        acc1.x = fmaf(b01.x, n1, acc1.x); acc1.y = fmaf(b01.y, n1, acc1.y);
        acc1.z = fmaf(b23.x, n1, acc1.z); acc1.w = fmaf(b23.y, n1, acc1.w);
        acc0.x = fmaf(c01.x, n2, acc0.x); acc0.y = fmaf(c01.y, n2, acc0.y);
        acc0.z = fmaf(c23.x, n2, acc0.z); acc0.w = fmaf(c23.y, n2, acc0.w);
        acc1.x = fmaf(d01.x, n3, acc1.x); acc1.y = fmaf(d01.y, n3, acc1.y);
        acc1.z = fmaf(d23.x, n3, acc1.z); acc1.w = fmaf(d23.y, n3, acc1.w);
    }
    for (; p < p1; p++) {
        int2 e0 = g_epack[p];
        uint2 a = __ldg(&h2[(size_t)e0.x * 32 + lane]);
        float n0 = __int_as_float(e0.y);
        float2 a01 = __half22float2(*(const __half2*)&a.x);
        float2 a23 = __half22float2(*(const __half2*)&a.y);
        acc0.x = fmaf(a01.x, n0, acc0.x); acc0.y = fmaf(a01.y, n0, acc0.y);
        acc0.z = fmaf(a23.x, n0, acc0.z); acc0.w = fmaf(a23.y, n0, acc0.w);
    }
    float4 bv = ((const float4*)bias)[lane];
    acc0.x += acc1.x + bv.x; acc0.y += acc1.y + bv.y;
    acc0.z += acc1.z + bv.z; acc0.w += acc1.w + bv.w;
    __half2 o01 = __floats2half2_rn(acc0.x, acc0.y);
    __half2 o23 = __floats2half2_rn(acc0.z, acc0.w);
    ((uint2*)outh)[(size_t)node * 32 + lane] =
        make_uint2(*(unsigned*)&o01, *(unsigned*)&o23);
}

// ---------------- aggregation fp32, fout=40 (reads padded stride 48) ----------------
__global__ void k_agg40(const float* __restrict__ h, const float* __restrict__ bias,
                        const float* __restrict__ dinv, float* __restrict__ out,
                        int n) {
    int node = (blockIdx.x * blockDim.x + threadIdx.x) >> 5;
    int lane = threadIdx.x & 31;
    if (node >= n || lane >= 20) return;
    float dv = dinv[node];
    float selfn = dv * dv;
    float2 sv = __ldg((const float2*)(h + (size_t)node * FO3P) + lane);
    float2 acc0 = make_float2(sv.x * selfn, sv.y * selfn);
    float2 acc1 = make_float2(0.f, 0.f);

    int p = g_rowptr[node], p1 = g_rowptr[node + 1];
    for (; p + 4 <= p1; p += 4) {
        int2 e0 = g_epack[p],     e1 = g_epack[p + 1];
        int2 e2 = g_epack[p + 2], e3 = g_epack[p + 3];
        float2 a = __ldg((const float2*)(h + (size_t)e0.x * FO3P) + lane);
        float2 b = __ldg((const float2*)(h + (size_t)e1.x * FO3P) + lane);
        float2 c = __ldg((const float2*)(h + (size_t)e2.x * FO3P) + lane);
        float2 d = __ldg((const float2*)(h + (size_t)e3.x * FO3P) + lane);
        float n0 = __int_as_float(e0.y), n1 = __int_as_float(e1.y);
        float n2 = __int_as_float(e2.y), n3 = __int_as_float(e3.y);
        acc0.x = fmaf(a.x, n0, acc0.x); acc0.y = fmaf(a.y, n0, acc0.y);
        acc1.x = fmaf(b.x, n1, acc1.x); acc1.y = fmaf(b.y, n1, acc1.y);
        acc0.x = fmaf(c.x, n2, acc0.x); acc0.y = fmaf(c.y, n2, acc0.y);
        acc1.x = fmaf(d.x, n3, acc1.x); acc1.y = fmaf(d.y, n3, acc1.y);
    }
    for (; p < p1; p++) {
        int2 e0 = g_epack[p];
        float2 a = __ldg((const float2*)(h + (size_t)e0.x * FO3P) + lane);
        float n0 = __int_as_float(e0.y);
        acc0.x = fmaf(a.x, n0, acc0.x); acc0.y = fmaf(a.y, n0, acc0.y);
    }
    float2 bv = ((const float2*)bias)[lane];
    acc0.x += acc1.x + bv.x; acc0.y += acc1.y + bv.y;
    ((float2*)(out + (size_t)node * FO3))[lane] = acc0;
}

// ---------------- launch ----------------
extern "C" void kernel_launch(void* const* d_in, const int* in_sizes, int n_in,
                              void* d_out, int out_size) {
    const float* x  = (const float*)d_in[0];
    const void*  ei = d_in[1];
    const float* ew = (const float*)d_in[2];
    const float* W1 = (const float*)d_in[3];
    const float* b1 = (const float*)d_in[4];
    const float* W2 = (const float*)d_in[5];
    const float* b2 = (const float*)d_in[6];
    const float* W3 = (const float*)d_in[7];
    const float* b3 = (const float*)d_in[8];
    int n  = in_sizes[0] / NF;
    int nE = in_sizes[2];
    float* out = (float*)d_out;

    float *dinv, *h32;
    __half *hh, *yh, *w2h, *w3h;
    int *rowptr, *cur, *cnt, *bsum, *is32p;
    cudaGetSymbolAddress((void**)&dinv, g_deg);
    cudaGetSymbolAddress((void**)&hh, g_hh);
    cudaGetSymbolAddress((void**)&h32, g_h32);
    cudaGetSymbolAddress((void**)&yh, g_yh);
    cudaGetSymbolAddress((void**)&w2h, g_w2h);
    cudaGetSymbolAddress((void**)&w3h, g_w3h);
    cudaGetSymbolAddress((void**)&rowptr, g_rowptr);
    cudaGetSymbolAddress((void**)&cur, g_cur);
    cudaGetSymbolAddress((void**)&cnt, g_cnt);
    cudaGetSymbolAddress((void**)&bsum, g_bsum);
    cudaGetSymbolAddress((void**)&is32p, g_is32);

    const int T = 256;
    size_t smemF32 = (size_t)(NF * NF + 8 * 8 * NF) * sizeof(float);  // 96 KB
    size_t smemTC128 = 48 * 1024;
    size_t smemTC40  = 44 * 1024;
    cudaFuncSetAttribute(k_gemm128_f32, cudaFuncAttributeMaxDynamicSharedMemorySize, (int)smemF32);
    cudaFuncSetAttribute(k_gemm128_tc,  cudaFuncAttributeMaxDynamicSharedMemorySize, (int)smemTC128);
    cudaFuncSetAttribute(k_gemm40_tc,   cudaFuncAttributeMaxDynamicSharedMemorySize, (int)smemTC40);

    int gb64  = (n + 63) / 64;
    int gb128 = (n + 127) / 128;
    int ab = (n + 7) / 8;  // 1 warp/node, 8 warps/block
    int nb = (n + 1023) / 1024;

    // Fork: GEMM1 (x@W1, fp32 FFMA2) independent of edge setup
    cudaStream_t s2;
    cudaStreamCreateWithFlags(&s2, cudaStreamNonBlocking);
    cudaEvent_t evF, evJ;
    cudaEventCreateWithFlags(&evF, cudaEventDisableTiming);
    cudaEventCreateWithFlags(&evJ, cudaEventDisableTiming);

    cudaEventRecord(evF, 0);
    cudaStreamWaitEvent(s2, evF, 0);
    k_gemm128_f32<<<gb64, T, smemF32, s2>>>(x, W1, hh, n);
    cudaEventRecord(evJ, s2);

    // Main-stream setup (overlapped with GEMM1)
    cudaMemsetAsync(is32p, 0, sizeof(int), 0);
    cudaMemsetAsync(cnt, 0, (size_t)n * sizeof(int), 0);
    cudaMemsetAsync(dinv, 0, (size_t)n * sizeof(float), 0);
    k_cvtW2<<<(NF * NF + T - 1) / T, T>>>(W2, w2h);
    k_cvtW3<<<(NF * FO3P + T - 1) / T, T>>>(W3, w3h);
    k_detect<<<(4096 + T - 1) / T, T>>>((const long long*)ei, nE);
    k_prep<<<(nE + T - 1) / T, T>>>(ei, ew, dinv, cnt, nE);
    k_dinv<<<(n + T - 1) / T, T>>>(dinv, n);
    k_scanA<<<nb, 1024>>>(cnt, rowptr, bsum, n);
    k_scanB<<<1, 128>>>(bsum, nb);
    k_scanC<<<(n + T - 1) / T, T>>>(rowptr, bsum, cur, n, nE);
    k_place<<<(nE + T - 1) / T, T>>>(ew, dinv, nE);

    cudaStreamWaitEvent(0, evJ, 0);

    // Layer 1 agg
    k_agg128h<<<ab, T>>>(hh, b1, dinv, yh, n);
    // Layer 2: tensor-core GEMM (ReLU fused) + agg
    k_gemm128_tc<<<gb64, T, smemTC128>>>(yh, w2h, hh, n);
    k_agg128h<<<ab, T>>>(hh, b2, dinv, yh, n);
    // Layer 3: tensor-core GEMM (padded 48) -> fp32, agg -> d_out
    k_gemm40_tc<<<gb128, T, smemTC40>>>(yh, w3h, h32, n);
    k_agg40<<<ab, T>>>(h32, b3, dinv, out, n);
}

// round 8
// speedup vs baseline: 1.1587x; 1.0031x over previous
#include <cuda_runtime.h>
#include <cuda_fp16.h>
#include <mma.h>
#include <cstdint>

using namespace nvcuda;

#define NN 100000
#define NE_CAP 1600000
#define NF 128
#define FO3 40
#define FO3P 48

typedef unsigned long long u64;

// ---------------- device scratch ----------------
__device__ float  g_deg[NN];
__device__ __half g_hh[(size_t)NN * NF];
__device__ float  g_h32[(size_t)NN * NF];   // layer-3 h, padded width 48
__device__ __half g_yh[(size_t)NN * NF];
__device__ __half g_w2h[NF * NF];
__device__ __half g_w3h[NF * FO3P];
__device__ int2   g_sd[NE_CAP];
__device__ int2   g_epack[NE_CAP];          // {src, f32-bits norm}, 16B-aligned base
__device__ int    g_rowptr[NN + 1];
__device__ int    g_cur[NN];
__device__ int    g_cnt[NN];
__device__ int    g_bsum[128];
__device__ int    g_is32;

// ---------------- f32x2 helpers ----------------
__device__ __forceinline__ void ffma2(u64& d, u64 a, u64 b) {
    asm("fma.rn.f32x2 %0, %1, %2, %0;" : "+l"(d) : "l"(a), "l"(b));
}
__device__ __forceinline__ u64 dup2(float x) {
    u64 r; asm("mov.b64 %0, {%1, %1};" : "=l"(r) : "f"(x)); return r;
}
__device__ __forceinline__ float2 upk2(u64 v) {
    float2 r; asm("mov.b64 {%0, %1}, %2;" : "=f"(r.x), "=f"(r.y) : "l"(v)); return r;
}

// ---------------- setup ----------------
__global__ void k_detect(const long long* __restrict__ raw, int nE) {
    int i = blockIdx.x * blockDim.x + threadIdx.x;
    int lim = nE < 4096 ? nE : 4096;
    if (i < lim) {
        long long v = raw[i];
        if (v < 0 || v >= (1LL << 30)) atomicOr(&g_is32, 1);
    }
}

__global__ void k_cvtW(const float* __restrict__ W2, const float* __restrict__ W3,
                       __half* __restrict__ W2h, __half* __restrict__ W3h) {
    int i = blockIdx.x * blockDim.x + threadIdx.x;
    if (i < NF * NF) W2h[i] = __float2half(W2[i]);
    int j = i - NF * NF;
    if (j >= 0 && j < NF * FO3P) {
        int r = j / FO3P, c = j - r * FO3P;
        W3h[j] = (c < FO3) ? __float2half(W3[r * FO3 + c]) : __half(0);
    }
}

__global__ void k_prep(const void* __restrict__ raw, const float* __restrict__ ew,
                       float* deg, int* cnt, int nE) {
    int e = blockIdx.x * blockDim.x + threadIdx.x;
    if (e >= nE) return;
    int s, d;
    if (g_is32) {
        const int* p = (const int*)raw;
        s = p[e]; d = p[(size_t)nE + e];
    } else {
        const long long* p = (const long long*)raw;
        s = (int)p[e]; d = (int)p[(size_t)nE + e];
    }
    g_sd[e] = make_int2(s, d);
    atomicAdd(&deg[d], ew[e]);
    atomicAdd(&cnt[d], 1);
}

__global__ void k_scanA(const int* __restrict__ cnt, int* rowptr, int* bsum, int n) {
    __shared__ int s[1024];
    int t = threadIdx.x, i = blockIdx.x * 1024 + t;
    int v = (i < n) ? cnt[i] : 0;
    s[t] = v;
    __syncthreads();
#pragma unroll
    for (int off = 1; off < 1024; off <<= 1) {
        int x = (t >= off) ? s[t - off] : 0;
        __syncthreads();
        s[t] += x;
        __syncthreads();
    }
    if (i < n) rowptr[i] = s[t] - v;
    if (t == 1023) bsum[blockIdx.x] = s[1023];
}

__global__ void k_scanB(int* bsum, int nb) {
    __shared__ int s[128];
    int t = threadIdx.x;
    int v = (t < nb) ? bsum[t] : 0;
    s[t] = v;
    __syncthreads();
#pragma unroll
    for (int off = 1; off < 128; off <<= 1) {
        int x = (t >= off) ? s[t - off] : 0;
        __syncthreads();
        s[t] += x;
        __syncthreads();
    }
    if (t < nb) bsum[t] = s[t] - v;
}

// scanC + dinv fused (both elementwise over nodes, both depend only on prep/scanB)
__global__ void k_scanC(int* rowptr, const int* __restrict__ bsum, int* cur,
                        float* deg, int n, int nE) {
    int i = blockIdx.x * blockDim.x + threadIdx.x;
    if (i < n) {
        int v = rowptr[i] + bsum[i >> 10];
        rowptr[i] = v;
        cur[i] = v;
        deg[i] = rsqrtf(deg[i] + 1.0f);
    }
    if (i == 0) rowptr[n] = nE;
}

__global__ void k_place(const float* __restrict__ ew, const float* __restrict__ dinv,
                        int nE) {
    int e = blockIdx.x * blockDim.x + threadIdx.x;
    if (e >= nE) return;
    int2 sd = g_sd[e];
    int p = atomicAdd(&g_cur[sd.y], 1);
    float norm = ew[e] * dinv[sd.x] * dinv[sd.y];
    g_epack[p] = make_int2(sd.x, __float_as_int(norm));
}

// ---------------- layer-1 GEMM (fp32, FFMA2) -> fp16 ----------------
__global__ void __launch_bounds__(256, 2)
k_gemm128_f32(const float* __restrict__ X, const float* __restrict__ W,
              __half* __restrict__ Hh, int n) {
    extern __shared__ float sm[];
    float* Ws = sm;
    float* Xs = sm + NF * NF;
    int tid = threadIdx.x, warp = tid >> 5, lane = tid & 31;

    for (int i = tid; i < NF * NF / 4; i += 256)
        ((float4*)Ws)[i] = ((const float4*)W)[i];

    int row0 = blockIdx.x * 64 + warp * 8;
    float* xs = Xs + warp * (8 * NF);
#pragma unroll
    for (int r = 0; r < 8; r++) {
        int row = row0 + r;
        float4 v = make_float4(0.f, 0.f, 0.f, 0.f);
        if (row < n) v = ((const float4*)(X + (size_t)row * NF))[lane];
        ((float4*)(xs + r * NF))[lane] = v;
    }
    __syncthreads();

    u64 acc[8][2];
#pragma unroll
    for (int r = 0; r < 8; r++) { acc[r][0] = 0ull; acc[r][1] = 0ull; }

    const float* wl = Ws + 4 * lane;
    for (int k4 = 0; k4 < NF; k4 += 4) {
        float4 xv[8];
#pragma unroll
        for (int r = 0; r < 8; r++)
            xv[r] = *(const float4*)(xs + r * NF + k4);
#pragma unroll
        for (int kk = 0; kk < 4; kk++) {
            const float* wp = wl + (k4 + kk) * NF;
            u64 w01 = *(const u64*)(wp);
            u64 w23 = *(const u64*)(wp + 2);
#pragma unroll
            for (int r = 0; r < 8; r++) {
                float xk = kk == 0 ? xv[r].x : kk == 1 ? xv[r].y
                         : kk == 2 ? xv[r].z : xv[r].w;
                u64 xk2 = dup2(xk);
                ffma2(acc[r][0], xk2, w01);
                ffma2(acc[r][1], xk2, w23);
            }
        }
    }
#pragma unroll
    for (int r = 0; r < 8; r++) {
        int row = row0 + r;
        if (row < n) {
            float2 a = upk2(acc[r][0]), b = upk2(acc[r][1]);
            __half2 h01 = __floats2half2_rn(a.x, a.y);
            __half2 h23 = __floats2half2_rn(b.x, b.y);
            ((uint2*)(Hh + (size_t)row * NF))[lane] =
                make_uint2(*(unsigned*)&h01, *(unsigned*)&h23);
        }
    }
}

// ---------------- tc GEMM fout=128 ----------------
__global__ void __launch_bounds__(256, 2)
k_gemm128_tc(const __half* __restrict__ X, const __half* __restrict__ W,
             __half* __restrict__ Hh, int n) {
    extern __shared__ char smc[];
    __half* Ws = (__half*)smc;
    __half* Xs = (__half*)(smc + 32 * 1024);
    int tid = threadIdx.x, wid = tid >> 5;
    int warp_m = wid >> 1, warp_n = wid & 1;
    int row0 = blockIdx.x * 64;

    for (int i = tid; i < 2048; i += 256)
        ((uint4*)Ws)[i] = ((const uint4*)W)[i];
    __half2 z2 = __floats2half2_rn(0.f, 0.f);
    for (int i = tid; i < 1024; i += 256) {
        int row = i >> 4, c = i & 15;
        uint4 v = make_uint4(0, 0, 0, 0);
        if (row0 + row < n) {
            v = ((const uint4*)(X + (size_t)(row0 + row) * NF))[c];
            __half2* hv = (__half2*)&v;
            hv[0] = __hmax2(hv[0], z2); hv[1] = __hmax2(hv[1], z2);
            hv[2] = __hmax2(hv[2], z2); hv[3] = __hmax2(hv[3], z2);
        }
        ((uint4*)Xs)[i] = v;
    }
    __syncthreads();

    wmma::fragment<wmma::accumulator, 16, 16, 16, float> c[4];
#pragma unroll
    for (int j = 0; j < 4; j++) wmma::fill_fragment(c[j], 0.f);

#pragma unroll
    for (int k0 = 0; k0 < NF; k0 += 16) {
        wmma::fragment<wmma::matrix_a, 16, 16, 16, __half, wmma::row_major> a;
        wmma::load_matrix_sync(a, Xs + warp_m * 16 * NF + k0, NF);
#pragma unroll
        for (int j = 0; j < 4; j++) {
            wmma::fragment<wmma::matrix_b, 16, 16, 16, __half, wmma::row_major> b;
            wmma::load_matrix_sync(b, Ws + k0 * NF + warp_n * 64 + j * 16, NF);
            wmma::mma_sync(c[j], a, b, c[j]);
        }
    }
    __syncthreads();
    float* Cs = (float*)smc;
#pragma unroll
    for (int j = 0; j < 4; j++)
        wmma::store_matrix_sync(Cs + warp_m * 16 * NF + warp_n * 64 + j * 16,
                                c[j], NF, wmma::mem_row_major);
    __syncthreads();

    for (int i = tid; i < 64 * 32; i += 256) {
        int row = i >> 5, g = i & 31;
        if (row0 + row < n) {
            float4 v = ((const float4*)Cs)[i];
            __half2 h01 = __floats2half2_rn(v.x, v.y);
            __half2 h23 = __floats2half2_rn(v.z, v.w);
            ((uint2*)(Hh + (size_t)(row0 + row) * NF))[g] =
                make_uint2(*(unsigned*)&h01, *(unsigned*)&h23);
        }
    }
}

// ---------------- tc GEMM fout=48 ----------------
__global__ void __launch_bounds__(256, 2)
k_gemm40_tc(const __half* __restrict__ X, const __half* __restrict__ W,
            float* __restrict__ H, int n) {
    extern __shared__ char smc[];
    __half* Ws = (__half*)smc;
    __half* Xs = (__half*)(smc + 12 * 1024);
    int tid = threadIdx.x, wid = tid >> 5;
    int row0 = blockIdx.x * 128;

    for (int i = tid; i < NF * FO3P / 8; i += 256)
        ((uint4*)Ws)[i] = ((const uint4*)W)[i];
    __half2 z2 = __floats2half2_rn(0.f, 0.f);
    for (int i = tid; i < 2048; i += 256) {
        int row = i >> 4, c = i & 15;
        uint4 v = make_uint4(0, 0, 0, 0);
        if (row0 + row < n) {
            v = ((const uint4*)(X + (size_t)(row0 + row) * NF))[c];
            __half2* hv = (__half2*)&v;
            hv[0] = __hmax2(hv[0], z2); hv[1] = __hmax2(hv[1], z2);
            hv[2] = __hmax2(hv[2], z2); hv[3] = __hmax2(hv[3], z2);
        }
        ((uint4*)Xs)[i] = v;
    }
    __syncthreads();

    wmma::fragment<wmma::accumulator, 16, 16, 16, float> c[3];
#pragma unroll
    for (int j = 0; j < 3; j++) wmma::fill_fragment(c[j], 0.f);

#pragma unroll
    for (int k0 = 0; k0 < NF; k0 += 16) {
        wmma::fragment<wmma::matrix_a, 16, 16, 16, __half, wmma::row_major> a;
        wmma::load_matrix_sync(a, Xs + wid * 16 * NF + k0, NF);
#pragma unroll
        for (int j = 0; j < 3; j++) {
            wmma::fragment<wmma::matrix_b, 16, 16, 16, __half, wmma::row_major> b;
            wmma::load_matrix_sync(b, Ws + k0 * FO3P + j * 16, FO3P);
            wmma::mma_sync(c[j], a, b, c[j]);
        }
    }
    __syncthreads();
    float* Cs = (float*)smc;
#pragma unroll
    for (int j = 0; j < 3; j++)
        wmma::store_matrix_sync(Cs + wid * 16 * FO3P + j * 16, c[j], FO3P,
                                wmma::mem_row_major);
    __syncthreads();

    for (int i = tid; i < 128 * 24; i += 256) {
        int row = i / 24, g = i - row * 24;
        if (row0 + row < n)
            ((float2*)(H + (size_t)(row0 + row) * FO3P))[g] = ((const float2*)Cs)[i];
    }
}

// ---------------- agg fp16, unroll-8 with int4 epack loads ----------------
__device__ __forceinline__ void agg_edge_h(const uint2* h2, int src, float nrm,
                                           int lane, float4& acc) {
    uint2 a = __ldg(&h2[(size_t)src * 32 + lane]);
    float2 a01 = __half22float2(*(const __half2*)&a.x);
    float2 a23 = __half22float2(*(const __half2*)&a.y);
    acc.x = fmaf(a01.x, nrm, acc.x); acc.y = fmaf(a01.y, nrm, acc.y);
    acc.z = fmaf(a23.x, nrm, acc.z); acc.w = fmaf(a23.y, nrm, acc.w);
}

__global__ void k_agg128h(const __half* __restrict__ h, const float* __restrict__ bias,
                          const float* __restrict__ dinv, __half* __restrict__ outh,
                          int n) {
    int node = (blockIdx.x * blockDim.x + threadIdx.x) >> 5;
    int lane = threadIdx.x & 31;
    if (node >= n) return;
    const uint2* h2 = (const uint2*)h;
    float dv = dinv[node];
    float selfn = dv * dv;

    uint2 sp = __ldg(&h2[(size_t)node * 32 + lane]);
    float2 s01 = __half22float2(*(const __half2*)&sp.x);
    float2 s23 = __half22float2(*(const __half2*)&sp.y);
    float4 acc0 = make_float4(s01.x * selfn, s01.y * selfn,
                              s23.x * selfn, s23.y * selfn);
    float4 acc1 = make_float4(0.f, 0.f, 0.f, 0.f);

    int p = g_rowptr[node], p1 = g_rowptr[node + 1];
    // peel to even p so int4 loads of epack are 16B-aligned
    if ((p & 1) && p < p1) {
        int2 e = g_epack[p];
        agg_edge_h(h2, e.x, __int_as_float(e.y), lane, acc0);
        p++;
    }
    const int4* ep4 = (const int4*)g_epack;
    for (; p + 8 <= p1; p += 8) {
        int h0 = p >> 1;
        int4 q0 = ep4[h0], q1 = ep4[h0 + 1], q2 = ep4[h0 + 2], q3 = ep4[h0 + 3];
        // 8 independent gathers in flight before any use
        uint2 a0 = __ldg(&h2[(size_t)q0.x * 32 + lane]);
        uint2 a1 = __ldg(&h2[(size_t)q0.z * 32 + lane]);
        uint2 a2 = __ldg(&h2[(size_t)q1.x * 32 + lane]);
        uint2 a3 = __ldg(&h2[(size_t)q1.z * 32 + lane]);
        uint2 a4 = __ldg(&h2[(size_t)q2.x * 32 + lane]);
        uint2 a5 = __ldg(&h2[(size_t)q2.z * 32 + lane]);
        uint2 a6 = __ldg(&h2[(size_t)q3.x * 32 + lane]);
        uint2 a7 = __ldg(&h2[(size_t)q3.z * 32 + lane]);
#define ACC_H(av, nbits, acc)                                           \
        {                                                               \
            float nrm = __int_as_float(nbits);                          \
            float2 u = __half22float2(*(const __half2*)&(av).x);        \
            float2 w = __half22float2(*(const __half2*)&(av).y);        \
            acc.x = fmaf(u.x, nrm, acc.x); acc.y = fmaf(u.y, nrm, acc.y); \
            acc.z = fmaf(w.x, nrm, acc.z); acc.w = fmaf(w.y, nrm, acc.w); \
        }
        ACC_H(a0, q0.y, acc0) ACC_H(a1, q0.w, acc1)
        ACC_H(a2, q1.y, acc0) ACC_H(a3, q1.w, acc1)
        ACC_H(a4, q2.y, acc0) ACC_H(a5, q2.w, acc1)
        ACC_H(a6, q3.y, acc0) ACC_H(a7, q3.w, acc1)
#undef ACC_H
    }
    for (; p < p1; p++) {
        int2 e = g_epack[p];
        agg_edge_h(h2, e.x, __int_as_float(e.y), lane, acc0);
    }
    float4 bv = ((const float4*)bias)[lane];
    acc0.x += acc1.x + bv.x; acc0.y += acc1.y + bv.y;
    acc0.z += acc1.z + bv.z; acc0.w += acc1.w + bv.w;
    __half2 o01 = __floats2half2_rn(acc0.x, acc0.y);
    __half2 o23 = __floats2half2_rn(acc0.z, acc0.w);
    ((uint2*)outh)[(size_t)node * 32 + lane] =
        make_uint2(*(unsigned*)&o01, *(unsigned*)&o23);
}

// ---------------- agg fp32 fout=40 (padded 48 input), unroll-8 ----------------
__global__ void k_agg40(const float* __restrict__ h, const float* __restrict__ bias,
                        const float* __restrict__ dinv, float* __restrict__ out,
                        int n) {
    int node = (blockIdx.x * blockDim.x + threadIdx.x) >> 5;
    int lane = threadIdx.x & 31;
    if (node >= n || lane >= 20) return;
    float dv = dinv[node];
    float selfn = dv * dv;
    float2 sv = __ldg((const float2*)(h + (size_t)node * FO3P) + lane);
    float2 acc0 = make_float2(sv.x * selfn, sv.y * selfn);
    float2 acc1 = make_float2(0.f, 0.f);

    int p = g_rowptr[node], p1 = g_rowptr[node + 1];
    if ((p & 1) && p < p1) {
        int2 e = g_epack[p];
        float2 a = __ldg((const float2*)(h + (size_t)e.x * FO3P) + lane);
        float nrm = __int_as_float(e.y);
        acc0.x = fmaf(a.x, nrm, acc0.x); acc0.y = fmaf(a.y, nrm, acc0.y);
        p++;
    }
    const int4* ep4 = (const int4*)g_epack;
    for (; p + 8 <= p1; p += 8) {
        int h0 = p >> 1;
        int4 q0 = ep4[h0], q1 = ep4[h0 + 1], q2 = ep4[h0 + 2], q3 = ep4[h0 + 3];
        float2 a0 = __ldg((const float2*)(h + (size_t)q0.x * FO3P) + lane);
        float2 a1 = __ldg((const float2*)(h + (size_t)q0.z * FO3P) + lane);
        float2 a2 = __ldg((const float2*)(h + (size_t)q1.x * FO3P) + lane);
        float2 a3 = __ldg((const float2*)(h + (size_t)q1.z * FO3P) + lane);
        float2 a4 = __ldg((const float2*)(h + (size_t)q2.x * FO3P) + lane);
        float2 a5 = __ldg((const float2*)(h + (size_t)q2.z * FO3P) + lane);
        float2 a6 = __ldg((const float2*)(h + (size_t)q3.x * FO3P) + lane);
        float2 a7 = __ldg((const float2*)(h + (size_t)q3.z * FO3P) + lane);
        float n0 = __int_as_float(q0.y), n1 = __int_as_float(q0.w);
        float n2 = __int_as_float(q1.y), n3 = __int_as_float(q1.w);
        float n4 = __int_as_float(q2.y), n5 = __int_as_float(q2.w);
        float n6 = __int_as_float(q3.y), n7 = __int_as_float(q3.w);
        acc0.x = fmaf(a0.x, n0, acc0.x); acc0.y = fmaf(a0.y, n0, acc0.y);
        acc1.x = fmaf(a1.x, n1, acc1.x); acc1.y = fmaf(a1.y, n1, acc1.y);
        acc0.x = fmaf(a2.x, n2, acc0.x); acc0.y = fmaf(a2.y, n2, acc0.y);
        acc1.x = fmaf(a3.x, n3, acc1.x); acc1.y = fmaf(a3.y, n3, acc1.y);
        acc0.x = fmaf(a4.x, n4, acc0.x); acc0.y = fmaf(a4.y, n4, acc0.y);
        acc1.x = fmaf(a5.x, n5, acc1.x); acc1.y = fmaf(a5.y, n5, acc1.y);
        acc0.x = fmaf(a6.x, n6, acc0.x); acc0.y = fmaf(a6.y, n6, acc0.y);
        acc1.x = fmaf(a7.x, n7, acc1.x); acc1.y = fmaf(a7.y, n7, acc1.y);
    }
    for (; p < p1; p++) {
        int2 e = g_epack[p];
        float2 a = __ldg((const float2*)(h + (size_t)e.x * FO3P) + lane);
        float nrm = __int_as_float(e.y);
        acc0.x = fmaf(a.x, nrm, acc0.x); acc0.y = fmaf(a.y, nrm, acc0.y);
    }
    float2 bv = ((const float2*)bias)[lane];
    acc0.x += acc1.x + bv.x; acc0.y += acc1.y + bv.y;
    ((float2*)(out + (size_t)node * FO3))[lane] = acc0;
}

// ---------------- launch ----------------
extern "C" void kernel_launch(void* const* d_in, const int* in_sizes, int n_in,
                              void* d_out, int out_size) {
    const float* x  = (const float*)d_in[0];
    const void*  ei = d_in[1];
    const float* ew = (const float*)d_in[2];
    const float* W1 = (const float*)d_in[3];
    const float* b1 = (const float*)d_in[4];
    const float* W2 = (const float*)d_in[5];
    const float* b2 = (const float*)d_in[6];
    const float* W3 = (const float*)d_in[7];
    const float* b3 = (const float*)d_in[8];
    int n  = in_sizes[0] / NF;
    int nE = in_sizes[2];
    float* out = (float*)d_out;

    float *dinv, *h32;
    __half *hh, *yh, *w2h, *w3h;
    int *rowptr, *cur, *cnt, *bsum, *is32p;
    cudaGetSymbolAddress((void**)&dinv, g_deg);
    cudaGetSymbolAddress((void**)&hh, g_hh);
    cudaGetSymbolAddress((void**)&h32, g_h32);
    cudaGetSymbolAddress((void**)&yh, g_yh);
    cudaGetSymbolAddress((void**)&w2h, g_w2h);
    cudaGetSymbolAddress((void**)&w3h, g_w3h);
    cudaGetSymbolAddress((void**)&rowptr, g_rowptr);
    cudaGetSymbolAddress((void**)&cur, g_cur);
    cudaGetSymbolAddress((void**)&cnt, g_cnt);
    cudaGetSymbolAddress((void**)&bsum, g_bsum);
    cudaGetSymbolAddress((void**)&is32p, g_is32);

    const int T = 256;
    size_t smemF32 = (size_t)(NF * NF + 8 * 8 * NF) * sizeof(float);
    size_t smemTC128 = 48 * 1024;
    size_t smemTC40  = 44 * 1024;
    cudaFuncSetAttribute(k_gemm128_f32, cudaFuncAttributeMaxDynamicSharedMemorySize, (int)smemF32);
    cudaFuncSetAttribute(k_gemm128_tc,  cudaFuncAttributeMaxDynamicSharedMemorySize, (int)smemTC128);
    cudaFuncSetAttribute(k_gemm40_tc,   cudaFuncAttributeMaxDynamicSharedMemorySize, (int)smemTC40);

    int gb64  = (n + 63) / 64;
    int gb128 = (n + 127) / 128;
    int ab = (n + 7) / 8;
    int nb = (n + 1023) / 1024;

    // Fork: GEMM1 independent of edge setup
    cudaStream_t s2;
    cudaStreamCreateWithFlags(&s2, cudaStreamNonBlocking);
    cudaEvent_t evF, evJ;
    cudaEventCreateWithFlags(&evF, cudaEventDisableTiming);
    cudaEventCreateWithFlags(&evJ, cudaEventDisableTiming);

    cudaEventRecord(evF, 0);
    cudaStreamWaitEvent(s2, evF, 0);
    k_gemm128_f32<<<gb64, T, smemF32, s2>>>(x, W1, hh, n);
    cudaEventRecord(evJ, s2);

    // Main-stream setup (overlapped with GEMM1)
    cudaMemsetAsync(is32p, 0, sizeof(int), 0);
    cudaMemsetAsync(cnt, 0, (size_t)n * sizeof(int), 0);
    cudaMemsetAsync(dinv, 0, (size_t)n * sizeof(float), 0);
    k_cvtW<<<(NF * NF + NF * FO3P + T - 1) / T, T>>>(W2, W3, w2h, w3h);
    k_detect<<<(4096 + T - 1) / T, T>>>((const long long*)ei, nE);
    k_prep<<<(nE + T - 1) / T, T>>>(ei, ew, dinv, cnt, nE);
    k_scanA<<<nb, 1024>>>(cnt, rowptr, bsum, n);
    k_scanB<<<1, 128>>>(bsum, nb);
    k_scanC<<<(n + T - 1) / T, T>>>(rowptr, bsum, cur, dinv, n, nE);
    k_place<<<(nE + T - 1) / T, T>>>(ew, dinv, nE);

    cudaStreamWaitEvent(0, evJ, 0);

    // Layer 1 agg
    k_agg128h<<<ab, T>>>(hh, b1, dinv, yh, n);
    // Layer 2
    k_gemm128_tc<<<gb64, T, smemTC128>>>(yh, w2h, hh, n);
    k_agg128h<<<ab, T>>>(hh, b2, dinv, yh, n);
    // Layer 3
    k_gemm40_tc<<<gb128, T, smemTC40>>>(yh, w3h, h32, n);
    k_agg40<<<ab, T>>>(h32, b3, dinv, out, n);
}

// round 9
// speedup vs baseline: 1.1661x; 1.0064x over previous
#include <cuda_runtime.h>
#include <cuda_fp16.h>
#include <mma.h>
#include <cstdint>

using namespace nvcuda;

#define NN 100000
#define NE_CAP 1600000
#define NF 128
#define FO3 40
#define FO3P 48

typedef unsigned long long u64;

// ---------------- device scratch ----------------
__device__ float  g_deg[NN];
__device__ __half g_hh[(size_t)NN * NF];
__device__ float  g_h32[(size_t)NN * NF];
__device__ __half g_yh[(size_t)NN * NF];
__device__ __half g_w2h[NF * NF];
__device__ __half g_w3h[NF * FO3P];
__device__ int2   g_sd[NE_CAP];
__device__ int2   g_epack[NE_CAP];
__device__ int    g_rowptr[NN + 1];
__device__ int    g_cur[NN];
__device__ int    g_cnt[NN];
__device__ int    g_bsum[128];
__device__ int    g_is32;

// ---------------- f32x2 helpers ----------------
__device__ __forceinline__ void ffma2(u64& d, u64 a, u64 b) {
    asm("fma.rn.f32x2 %0, %1, %2, %0;" : "+l"(d) : "l"(a), "l"(b));
}
__device__ __forceinline__ u64 dup2(float x) {
    u64 r; asm("mov.b64 %0, {%1, %1};" : "=l"(r) : "f"(x)); return r;
}
__device__ __forceinline__ float2 upk2(u64 v) {
    float2 r; asm("mov.b64 {%0, %1}, %2;" : "=f"(r.x), "=f"(r.y) : "l"(v)); return r;
}

// ---------------- fused init: zero deg/cnt + dtype detect + W2/W3 cvt ----------------
// Block 0 detects the edge dtype (plain store by thread 0 -> no cross-block race).
// All blocks grid-stride: zero deg/cnt over n, convert W2 (16384) + W3pad (6144).
__global__ void k_init(const long long* __restrict__ raw, int nE,
                       const float* __restrict__ W2, const float* __restrict__ W3,
                       __half* __restrict__ W2h, __half* __restrict__ W3h,
                       float* deg, int* cnt, int n) {
    int tid = threadIdx.x;
    int gid = blockIdx.x * blockDim.x + tid;
    int gsz = gridDim.x * blockDim.x;

    if (blockIdx.x == 0) {
        __shared__ int sflag;
        if (tid == 0) sflag = 0;
        __syncthreads();
        int lim = nE < 4096 ? nE : 4096;
        int bad = 0;
        for (int i = tid; i < lim; i += blockDim.x) {
            long long v = raw[i];
            if (v < 0 || v >= (1LL << 30)) bad = 1;
        }
        if (bad) atomicOr(&sflag, 1);
        __syncthreads();
        if (tid == 0) g_is32 = sflag;
    }

    for (int i = gid; i < n; i += gsz) { deg[i] = 0.f; cnt[i] = 0; }
    for (int i = gid; i < NF * NF; i += gsz) W2h[i] = __float2half(W2[i]);
    for (int i = gid; i < NF * FO3P; i += gsz) {
        int r = i / FO3P, c = i - r * FO3P;
        W3h[i] = (c < FO3) ? __float2half(W3[r * FO3 + c]) : __half(0);
    }
}

__global__ void k_prep(const void* __restrict__ raw, const float* __restrict__ ew,
                       float* deg, int* cnt, int nE) {
    int e = blockIdx.x * blockDim.x + threadIdx.x;
    if (e >= nE) return;
    int s, d;
    if (g_is32) {
        const int* p = (const int*)raw;
        s = p[e]; d = p[(size_t)nE + e];
    } else {
        const long long* p = (const long long*)raw;
        s = (int)p[e]; d = (int)p[(size_t)nE + e];
    }
    g_sd[e] = make_int2(s, d);
    atomicAdd(&deg[d], ew[e]);
    atomicAdd(&cnt[d], 1);
}

__global__ void k_scanA(const int* __restrict__ cnt, int* rowptr, int* bsum, int n) {
    __shared__ int s[1024];
    int t = threadIdx.x, i = blockIdx.x * 1024 + t;
    int v = (i < n) ? cnt[i] : 0;
    s[t] = v;
    __syncthreads();
#pragma unroll
    for (int off = 1; off < 1024; off <<= 1) {
        int x = (t >= off) ? s[t - off] : 0;
        __syncthreads();
        s[t] += x;
        __syncthreads();
    }
    if (i < n) rowptr[i] = s[t] - v;
    if (t == 1023) bsum[blockIdx.x] = s[1023];
}

// scanC with scanB folded in: every block redundantly scans the <=128-entry bsum
// in shared memory (exclusive), then applies offsets + computes dinv in place.
__global__ void k_scanCB(int* rowptr, const int* __restrict__ bsum, int* cur,
                         float* deg, int n, int nE, int nb) {
    __shared__ int sb[128];
    int t = threadIdx.x;
    if (t < 128) sb[t] = (t < nb) ? bsum[t] : 0;
    __syncthreads();
#pragma unroll
    for (int off = 1; off < 128; off <<= 1) {
        int x = 0;
        if (t < 128 && t >= off) x = sb[t - off];
        __syncthreads();
        if (t < 128) sb[t] += x;
        __syncthreads();
    }
    // sb now inclusive; exclusive offset for chunk j is sb[j-1] (0 for j=0)
    int i = blockIdx.x * blockDim.x + t;
    if (i < n) {
        int j = i >> 10;
        int off = (j == 0) ? 0 : sb[j - 1];
        int v = rowptr[i] + off;
        rowptr[i] = v;
        cur[i] = v;
        deg[i] = rsqrtf(deg[i] + 1.0f);
    }
    if (i == 0) rowptr[n] = nE;
}

__global__ void k_place(const float* __restrict__ ew, const float* __restrict__ dinv,
                        int nE) {
    int e = blockIdx.x * blockDim.x + threadIdx.x;
    if (e >= nE) return;
    int2 sd = g_sd[e];
    int p = atomicAdd(&g_cur[sd.y], 1);
    float norm = ew[e] * dinv[sd.x] * dinv[sd.y];
    g_epack[p] = make_int2(sd.x, __float_as_int(norm));
}

// ---------------- layer-1 GEMM (fp32, FFMA2) -> fp16 ----------------
__global__ void __launch_bounds__(256, 2)
k_gemm128_f32(const float* __restrict__ X, const float* __restrict__ W,
              __half* __restrict__ Hh, int n) {
    extern __shared__ float sm[];
    float* Ws = sm;
    float* Xs = sm + NF * NF;
    int tid = threadIdx.x, warp = tid >> 5, lane = tid & 31;

    for (int i = tid; i < NF * NF / 4; i += 256)
        ((float4*)Ws)[i] = ((const float4*)W)[i];

    int row0 = blockIdx.x * 64 + warp * 8;
    float* xs = Xs + warp * (8 * NF);
#pragma unroll
    for (int r = 0; r < 8; r++) {
        int row = row0 + r;
        float4 v = make_float4(0.f, 0.f, 0.f, 0.f);
        if (row < n) v = ((const float4*)(X + (size_t)row * NF))[lane];
        ((float4*)(xs + r * NF))[lane] = v;
    }
    __syncthreads();

    u64 acc[8][2];
#pragma unroll
    for (int r = 0; r < 8; r++) { acc[r][0] = 0ull; acc[r][1] = 0ull; }

    const float* wl = Ws + 4 * lane;
    for (int k4 = 0; k4 < NF; k4 += 4) {
        float4 xv[8];
#pragma unroll
        for (int r = 0; r < 8; r++)
            xv[r] = *(const float4*)(xs + r * NF + k4);
#pragma unroll
        for (int kk = 0; kk < 4; kk++) {
            const float* wp = wl + (k4 + kk) * NF;
            u64 w01 = *(const u64*)(wp);
            u64 w23 = *(const u64*)(wp + 2);
#pragma unroll
            for (int r = 0; r < 8; r++) {
                float xk = kk == 0 ? xv[r].x : kk == 1 ? xv[r].y
                         : kk == 2 ? xv[r].z : xv[r].w;
                u64 xk2 = dup2(xk);
                ffma2(acc[r][0], xk2, w01);
                ffma2(acc[r][1], xk2, w23);
            }
        }
    }
#pragma unroll
    for (int r = 0; r < 8; r++) {
        int row = row0 + r;
        if (row < n) {
            float2 a = upk2(acc[r][0]), b = upk2(acc[r][1]);
            __half2 h01 = __floats2half2_rn(a.x, a.y);
            __half2 h23 = __floats2half2_rn(b.x, b.y);
            ((uint2*)(Hh + (size_t)row * NF))[lane] =
                make_uint2(*(unsigned*)&h01, *(unsigned*)&h23);
        }
    }
}

// ---------------- tc GEMM fout=128 ----------------
__global__ void __launch_bounds__(256, 2)
k_gemm128_tc(const __half* __restrict__ X, const __half* __restrict__ W,
             __half* __restrict__ Hh, int n) {
    extern __shared__ char smc[];
    __half* Ws = (__half*)smc;
    __half* Xs = (__half*)(smc + 32 * 1024);
    int tid = threadIdx.x, wid = tid >> 5;
    int warp_m = wid >> 1, warp_n = wid & 1;
    int row0 = blockIdx.x * 64;

    for (int i = tid; i < 2048; i += 256)
        ((uint4*)Ws)[i] = ((const uint4*)W)[i];
    __half2 z2 = __floats2half2_rn(0.f, 0.f);
    for (int i = tid; i < 1024; i += 256) {
        int row = i >> 4, c = i & 15;
        uint4 v = make_uint4(0, 0, 0, 0);
        if (row0 + row < n) {
            v = ((const uint4*)(X + (size_t)(row0 + row) * NF))[c];
            __half2* hv = (__half2*)&v;
            hv[0] = __hmax2(hv[0], z2); hv[1] = __hmax2(hv[1], z2);
            hv[2] = __hmax2(hv[2], z2); hv[3] = __hmax2(hv[3], z2);
        }
        ((uint4*)Xs)[i] = v;
    }
    __syncthreads();

    wmma::fragment<wmma::accumulator, 16, 16, 16, float> c[4];
#pragma unroll
    for (int j = 0; j < 4; j++) wmma::fill_fragment(c[j], 0.f);

#pragma unroll
    for (int k0 = 0; k0 < NF; k0 += 16) {
        wmma::fragment<wmma::matrix_a, 16, 16, 16, __half, wmma::row_major> a;
        wmma::load_matrix_sync(a, Xs + warp_m * 16 * NF + k0, NF);
#pragma unroll
        for (int j = 0; j < 4; j++) {
            wmma::fragment<wmma::matrix_b, 16, 16, 16, __half, wmma::row_major> b;
            wmma::load_matrix_sync(b, Ws + k0 * NF + warp_n * 64 + j * 16, NF);
            wmma::mma_sync(c[j], a, b, c[j]);
        }
    }
    __syncthreads();
    float* Cs = (float*)smc;
#pragma unroll
    for (int j = 0; j < 4; j++)
        wmma::store_matrix_sync(Cs + warp_m * 16 * NF + warp_n * 64 + j * 16,
                                c[j], NF, wmma::mem_row_major);
    __syncthreads();

    for (int i = tid; i < 64 * 32; i += 256) {
        int row = i >> 5, g = i & 31;
        if (row0 + row < n) {
            float4 v = ((const float4*)Cs)[i];
            __half2 h01 = __floats2half2_rn(v.x, v.y);
            __half2 h23 = __floats2half2_rn(v.z, v.w);
            ((uint2*)(Hh + (size_t)(row0 + row) * NF))[g] =
                make_uint2(*(unsigned*)&h01, *(unsigned*)&h23);
        }
    }
}

// ---------------- tc GEMM fout=48 ----------------
__global__ void __launch_bounds__(256, 2)
k_gemm40_tc(const __half* __restrict__ X, const __half* __restrict__ W,
            float* __restrict__ H, int n) {
    extern __shared__ char smc[];
    __half* Ws = (__half*)smc;
    __half* Xs = (__half*)(smc + 12 * 1024);
    int tid = threadIdx.x, wid = tid >> 5;
    int row0 = blockIdx.x * 128;

    for (int i = tid; i < NF * FO3P / 8; i += 256)
        ((uint4*)Ws)[i] = ((const uint4*)W)[i];
    __half2 z2 = __floats2half2_rn(0.f, 0.f);
    for (int i = tid; i < 2048; i += 256) {
        int row = i >> 4, c = i & 15;
        uint4 v = make_uint4(0, 0, 0, 0);
        if (row0 + row < n) {
            v = ((const uint4*)(X + (size_t)(row0 + row) * NF))[c];
            __half2* hv = (__half2*)&v;
            hv[0] = __hmax2(hv[0], z2); hv[1] = __hmax2(hv[1], z2);
            hv[2] = __hmax2(hv[2], z2); hv[3] = __hmax2(hv[3], z2);
        }
        ((uint4*)Xs)[i] = v;
    }
    __syncthreads();

    wmma::fragment<wmma::accumulator, 16, 16, 16, float> c[3];
#pragma unroll
    for (int j = 0; j < 3; j++) wmma::fill_fragment(c[j], 0.f);

#pragma unroll
    for (int k0 = 0; k0 < NF; k0 += 16) {
        wmma::fragment<wmma::matrix_a, 16, 16, 16, __half, wmma::row_major> a;
        wmma::load_matrix_sync(a, Xs + wid * 16 * NF + k0, NF);
#pragma unroll
        for (int j = 0; j < 3; j++) {
            wmma::fragment<wmma::matrix_b, 16, 16, 16, __half, wmma::row_major> b;
            wmma::load_matrix_sync(b, Ws + k0 * FO3P + j * 16, FO3P);
            wmma::mma_sync(c[j], a, b, c[j]);
        }
    }
    __syncthreads();
    float* Cs = (float*)smc;
#pragma unroll
    for (int j = 0; j < 3; j++)
        wmma::store_matrix_sync(Cs + wid * 16 * FO3P + j * 16, c[j], FO3P,
                                wmma::mem_row_major);
    __syncthreads();

    for (int i = tid; i < 128 * 24; i += 256) {
        int row = i / 24, g = i - row * 24;
        if (row0 + row < n)
            ((float2*)(H + (size_t)(row0 + row) * FO3P))[g] = ((const float2*)Cs)[i];
    }
}

// ---------------- agg fp16 (R8-identical) ----------------
__device__ __forceinline__ void agg_edge_h(const uint2* h2, int src, float nrm,
                                           int lane, float4& acc) {
    uint2 a = __ldg(&h2[(size_t)src * 32 + lane]);
    float2 a01 = __half22float2(*(const __half2*)&a.x);
    float2 a23 = __half22float2(*(const __half2*)&a.y);
    acc.x = fmaf(a01.x, nrm, acc.x); acc.y = fmaf(a01.y, nrm, acc.y);
    acc.z = fmaf(a23.x, nrm, acc.z); acc.w = fmaf(a23.y, nrm, acc.w);
}

__global__ void k_agg128h(const __half* __restrict__ h, const float* __restrict__ bias,
                          const float* __restrict__ dinv, __half* __restrict__ outh,
                          int n) {
    int node = (blockIdx.x * blockDim.x + threadIdx.x) >> 5;
    int lane = threadIdx.x & 31;
    if (node >= n) return;
    const uint2* h2 = (const uint2*)h;
    float dv = dinv[node];
    float selfn = dv * dv;

    uint2 sp = __ldg(&h2[(size_t)node * 32 + lane]);
    float2 s01 = __half22float2(*(const __half2*)&sp.x);
    float2 s23 = __half22float2(*(const __half2*)&sp.y);
    float4 acc0 = make_float4(s01.x * selfn, s01.y * selfn,
                              s23.x * selfn, s23.y * selfn);
    float4 acc1 = make_float4(0.f, 0.f, 0.f, 0.f);

    int p = g_rowptr[node], p1 = g_rowptr[node + 1];
    if ((p & 1) && p < p1) {
        int2 e = g_epack[p];
        agg_edge_h(h2, e.x, __int_as_float(e.y), lane, acc0);
        p++;
    }
    const int4* ep4 = (const int4*)g_epack;
    for (; p + 8 <= p1; p += 8) {
        int h0 = p >> 1;
        int4 q0 = ep4[h0], q1 = ep4[h0 + 1], q2 = ep4[h0 + 2], q3 = ep4[h0 + 3];
        uint2 a0 = __ldg(&h2[(size_t)q0.x * 32 + lane]);
        uint2 a1 = __ldg(&h2[(size_t)q0.z * 32 + lane]);
        uint2 a2 = __ldg(&h2[(size_t)q1.x * 32 + lane]);
        uint2 a3 = __ldg(&h2[(size_t)q1.z * 32 + lane]);
        uint2 a4 = __ldg(&h2[(size_t)q2.x * 32 + lane]);
        uint2 a5 = __ldg(&h2[(size_t)q2.z * 32 + lane]);
        uint2 a6 = __ldg(&h2[(size_t)q3.x * 32 + lane]);
        uint2 a7 = __ldg(&h2[(size_t)q3.z * 32 + lane]);
#define ACC_H(av, nbits, acc)                                           \
        {                                                               \
            float nrm = __int_as_float(nbits);                          \
            float2 u = __half22float2(*(const __half2*)&(av).x);        \
            float2 w = __half22float2(*(const __half2*)&(av).y);        \
            acc.x = fmaf(u.x, nrm, acc.x); acc.y = fmaf(u.y, nrm, acc.y); \
            acc.z = fmaf(w.x, nrm, acc.z); acc.w = fmaf(w.y, nrm, acc.w); \
        }
        ACC_H(a0, q0.y, acc0) ACC_H(a1, q0.w, acc1)
        ACC_H(a2, q1.y, acc0) ACC_H(a3, q1.w, acc1)
        ACC_H(a4, q2.y, acc0) ACC_H(a5, q2.w, acc1)
        ACC_H(a6, q3.y, acc0) ACC_H(a7, q3.w, acc1)
#undef ACC_H
    }
    for (; p < p1; p++) {
        int2 e = g_epack[p];
        agg_edge_h(h2, e.x, __int_as_float(e.y), lane, acc0);
    }
    float4 bv = ((const float4*)bias)[lane];
    acc0.x += acc1.x + bv.x; acc0.y += acc1.y + bv.y;
    acc0.z += acc1.z + bv.z; acc0.w += acc1.w + bv.w;
    __half2 o01 = __floats2half2_rn(acc0.x, acc0.y);
    __half2 o23 = __floats2half2_rn(acc0.z, acc0.w);
    ((uint2*)outh)[(size_t)node * 32 + lane] =
        make_uint2(*(unsigned*)&o01, *(unsigned*)&o23);
}

// ---------------- agg fp32 fout=40 (R8-identical) ----------------
__global__ void k_agg40(const float* __restrict__ h, const float* __restrict__ bias,
                        const float* __restrict__ dinv, float* __restrict__ out,
                        int n) {
    int node = (blockIdx.x * blockDim.x + threadIdx.x) >> 5;
    int lane = threadIdx.x & 31;
    if (node >= n || lane >= 20) return;
    float dv = dinv[node];
    float selfn = dv * dv;
    float2 sv = __ldg((const float2*)(h + (size_t)node * FO3P) + lane);
    float2 acc0 = make_float2(sv.x * selfn, sv.y * selfn);
    float2 acc1 = make_float2(0.f, 0.f);

    int p = g_rowptr[node], p1 = g_rowptr[node + 1];
    if ((p & 1) && p < p1) {
        int2 e = g_epack[p];
        float2 a = __ldg((const float2*)(h + (size_t)e.x * FO3P) + lane);
        float nrm = __int_as_float(e.y);
        acc0.x = fmaf(a.x, nrm, acc0.x); acc0.y = fmaf(a.y, nrm, acc0.y);
        p++;
    }
    const int4* ep4 = (const int4*)g_epack;
    for (; p + 8 <= p1; p += 8) {
        int h0 = p >> 1;
        int4 q0 = ep4[h0], q1 = ep4[h0 + 1], q2 = ep4[h0 + 2], q3 = ep4[h0 + 3];
        float2 a0 = __ldg((const float2*)(h + (size_t)q0.x * FO3P) + lane);
        float2 a1 = __ldg((const float2*)(h + (size_t)q0.z * FO3P) + lane);
        float2 a2 = __ldg((const float2*)(h + (size_t)q1.x * FO3P) + lane);
        float2 a3 = __ldg((const float2*)(h + (size_t)q1.z * FO3P) + lane);
        float2 a4 = __ldg((const float2*)(h + (size_t)q2.x * FO3P) + lane);
        float2 a5 = __ldg((const float2*)(h + (size_t)q2.z * FO3P) + lane);
        float2 a6 = __ldg((const float2*)(h + (size_t)q3.x * FO3P) + lane);
        float2 a7 = __ldg((const float2*)(h + (size_t)q3.z * FO3P) + lane);
        float n0 = __int_as_float(q0.y), n1 = __int_as_float(q0.w);
        float n2 = __int_as_float(q1.y), n3 = __int_as_float(q1.w);
        float n4 = __int_as_float(q2.y), n5 = __int_as_float(q2.w);
        float n6 = __int_as_float(q3.y), n7 = __int_as_float(q3.w);
        acc0.x = fmaf(a0.x, n0, acc0.x); acc0.y = fmaf(a0.y, n0, acc0.y);
        acc1.x = fmaf(a1.x, n1, acc1.x); acc1.y = fmaf(a1.y, n1, acc1.y);
        acc0.x = fmaf(a2.x, n2, acc0.x); acc0.y = fmaf(a2.y, n2, acc0.y);
        acc1.x = fmaf(a3.x, n3, acc1.x); acc1.y = fmaf(a3.y, n3, acc1.y);
        acc0.x = fmaf(a4.x, n4, acc0.x); acc0.y = fmaf(a4.y, n4, acc0.y);
        acc1.x = fmaf(a5.x, n5, acc1.x); acc1.y = fmaf(a5.y, n5, acc1.y);
        acc0.x = fmaf(a6.x, n6, acc0.x); acc0.y = fmaf(a6.y, n6, acc0.y);
        acc1.x = fmaf(a7.x, n7, acc1.x); acc1.y = fmaf(a7.y, n7, acc1.y);
    }
    for (; p < p1; p++) {
        int2 e = g_epack[p];
        float2 a = __ldg((const float2*)(h + (size_t)e.x * FO3P) + lane);
        float nrm = __int_as_float(e.y);
        acc0.x = fmaf(a.x, nrm, acc0.x); acc0.y = fmaf(a.y, nrm, acc0.y);
    }
    float2 bv = ((const float2*)bias)[lane];
    acc0.x += acc1.x + bv.x; acc0.y += acc1.y + bv.y;
    ((float2*)(out + (size_t)node * FO3))[lane] = acc0;
}

// ---------------- launch ----------------
extern "C" void kernel_launch(void* const* d_in, const int* in_sizes, int n_in,
                              void* d_out, int out_size) {
    const float* x  = (const float*)d_in[0];
    const void*  ei = d_in[1];
    const float* ew = (const float*)d_in[2];
    const float* W1 = (const float*)d_in[3];
    const float* b1 = (const float*)d_in[4];
    const float* W2 = (const float*)d_in[5];
    const float* b2 = (const float*)d_in[6];
    const float* W3 = (const float*)d_in[7];
    const float* b3 = (const float*)d_in[8];
    int n  = in_sizes[0] / NF;
    int nE = in_sizes[2];
    float* out = (float*)d_out;

    float *dinv, *h32;
    __half *hh, *yh, *w2h, *w3h;
    int *rowptr, *cur, *cnt, *bsum;
    cudaGetSymbolAddress((void**)&dinv, g_deg);
    cudaGetSymbolAddress((void**)&hh, g_hh);
    cudaGetSymbolAddress((void**)&h32, g_h32);
    cudaGetSymbolAddress((void**)&yh, g_yh);
    cudaGetSymbolAddress((void**)&w2h, g_w2h);
    cudaGetSymbolAddress((void**)&w3h, g_w3h);
    cudaGetSymbolAddress((void**)&rowptr, g_rowptr);
    cudaGetSymbolAddress((void**)&cur, g_cur);
    cudaGetSymbolAddress((void**)&cnt, g_cnt);
    cudaGetSymbolAddress((void**)&bsum, g_bsum);

    const int T = 256;
    size_t smemF32 = (size_t)(NF * NF + 8 * 8 * NF) * sizeof(float);
    size_t smemTC128 = 48 * 1024;
    size_t smemTC40  = 44 * 1024;
    cudaFuncSetAttribute(k_gemm128_f32, cudaFuncAttributeMaxDynamicSharedMemorySize, (int)smemF32);
    cudaFuncSetAttribute(k_gemm128_tc,  cudaFuncAttributeMaxDynamicSharedMemorySize, (int)smemTC128);
    cudaFuncSetAttribute(k_gemm40_tc,   cudaFuncAttributeMaxDynamicSharedMemorySize, (int)smemTC40);

    int gb64  = (n + 63) / 64;
    int gb128 = (n + 127) / 128;
    int ab = (n + 7) / 8;
    int nb = (n + 1023) / 1024;

    cudaStream_t s2;
    cudaStreamCreateWithFlags(&s2, cudaStreamNonBlocking);
    cudaEvent_t evF, evJ;
    cudaEventCreateWithFlags(&evF, cudaEventDisableTiming);
    cudaEventCreateWithFlags(&evJ, cudaEventDisableTiming);

    // Root event first: the s2 branch (GEMM1) depends only on this, so it
    // overlaps the whole setup chain at replay regardless of code order below.
    cudaEventRecord(evF, 0);

    // Setup chain (5 kernels) — capture window (-s 5) lands on the kernel
    // right after these: k_agg128h.
    k_init<<<(n + T - 1) / T, T>>>((const long long*)ei, nE, W2, W3, w2h, w3h,
                                   dinv, cnt, n);
    k_prep<<<(nE + T - 1) / T, T>>>(ei, ew, dinv, cnt, nE);
    k_scanA<<<nb, 1024>>>(cnt, rowptr, bsum, n);
    k_scanCB<<<(n + T - 1) / T, T>>>(rowptr, bsum, cur, dinv, n, nE, nb);
    k_place<<<(nE + T - 1) / T, T>>>(ew, dinv, nE);

    // Fork branch: GEMM1 (x@W1), independent of edge setup.
    cudaStreamWaitEvent(s2, evF, 0);
    k_gemm128_f32<<<gb64, T, smemF32, s2>>>(x, W1, hh, n);
    cudaEventRecord(evJ, s2);
    cudaStreamWaitEvent(0, evJ, 0);

    // Layer 1 agg
    k_agg128h<<<ab, T>>>(hh, b1, dinv, yh, n);
    // Layer 2
    k_gemm128_tc<<<gb64, T, smemTC128>>>(yh, w2h, hh, n);
    k_agg128h<<<ab, T>>>(hh, b2, dinv, yh, n);
    // Layer 3
    k_gemm40_tc<<<gb128, T, smemTC40>>>(yh, w3h, h32, n);
    k_agg40<<<ab, T>>>(h32, b3, dinv, out, n);
}